// round 1
// baseline (speedup 1.0000x reference)
#include <cuda_runtime.h>
#include <math.h>
#include <math_constants.h>

#define SEQ   1365
#define DIMD  1024
#define NH    16
#define HD    64
#define NB    8
#define MROWS (NB*SEQ)   // 10920

// ---------------- scratch (device globals: no allocations allowed) ----------
__device__ float g_wb [NB * 2 * DIMD];          // adaLN w|b per batch
__device__ float g_xn [ (size_t)MROWS * DIMD ]; // modulated layernorm output
__device__ float g_qkv[ (size_t)MROWS * 3 * DIMD ];
__device__ float g_oa [ (size_t)MROWS * DIMD ]; // attention output (B,S,H*D)

// ---------------- helpers ---------------------------------------------------
__device__ __forceinline__ int block_end(int s) {
    if (s < 1)   return 1;
    if (s < 5)   return 5;
    if (s < 21)  return 21;
    if (s < 85)  return 85;
    if (s < 341) return 341;
    return 1365;
}

// ---------------- adaLN: wb[b] = cond[b] @ adaln_w + adaln_b ----------------
__global__ void adaln_kernel(const float* __restrict__ cond,
                             const float* __restrict__ w,
                             const float* __restrict__ bias) {
    __shared__ float c[256];
    int b = blockIdx.x;
    int t = threadIdx.x;
    c[t] = cond[b * 256 + t];
    __syncthreads();
    for (int j = t; j < 2048; j += 256) {
        float acc = bias[j];
        #pragma unroll 8
        for (int k = 0; k < 256; k++) acc += c[k] * w[k * 2048 + j];
        g_wb[b * 2048 + j] = acc;
    }
}

// ---------------- LayerNorm + modulate --------------------------------------
__global__ void ln_kernel(const float* __restrict__ x) {
    int row = blockIdx.x;           // 0..MROWS-1
    int b   = row / SEQ;
    int t   = threadIdx.x;          // 256
    const float4* xr = (const float4*)(x + (size_t)row * DIMD);
    float4 v = xr[t];
    float s  = v.x + v.y + v.z + v.w;
    float ss = v.x*v.x + v.y*v.y + v.z*v.z + v.w*v.w;
    #pragma unroll
    for (int o = 16; o > 0; o >>= 1) {
        s  += __shfl_down_sync(0xffffffffu, s,  o);
        ss += __shfl_down_sync(0xffffffffu, ss, o);
    }
    __shared__ float sh_s[8], sh_ss[8];
    int w = t >> 5, ln = t & 31;
    if (ln == 0) { sh_s[w] = s; sh_ss[w] = ss; }
    __syncthreads();
    if (w == 0) {
        s  = (ln < 8) ? sh_s[ln]  : 0.f;
        ss = (ln < 8) ? sh_ss[ln] : 0.f;
        #pragma unroll
        for (int o = 4; o > 0; o >>= 1) {
            s  += __shfl_down_sync(0xffffffffu, s,  o);
            ss += __shfl_down_sync(0xffffffffu, ss, o);
        }
        if (ln == 0) { sh_s[0] = s; sh_ss[0] = ss; }
    }
    __syncthreads();
    float mu   = sh_s[0]  * (1.0f / 1024.0f);
    float var  = sh_ss[0] * (1.0f / 1024.0f) - mu * mu;
    float rstd = rsqrtf(var + 1e-5f);
    const float4* wr = (const float4*)(g_wb + b * 2048);
    float4 wv = wr[t];
    float4 bv = wr[256 + t];
    float4 r;
    r.x = (v.x - mu) * rstd * (wv.x + 1.0f) + bv.x;
    r.y = (v.y - mu) * rstd * (wv.y + 1.0f) + bv.y;
    r.z = (v.z - mu) * rstd * (wv.z + 1.0f) + bv.z;
    r.w = (v.w - mu) * rstd * (wv.w + 1.0f) + bv.w;
    ((float4*)(g_xn + (size_t)row * DIMD))[t] = r;
}

// ---------------- generic fp32 GEMM: C = A@W + bias (+ skip) ----------------
__global__ __launch_bounds__(256)
void gemm_kernel(const float* __restrict__ A, const float* __restrict__ W,
                 const float* __restrict__ bias, const float* __restrict__ skip,
                 float* __restrict__ C, int M, int N, int K) {
    __shared__ float As[8][132];
    __shared__ float Ws[8][128];
    int t  = threadIdx.x;
    int tx = t & 15, ty = t >> 4;
    int m0 = blockIdx.y * 128, n0 = blockIdx.x * 128;
    float acc[8][8];
    #pragma unroll
    for (int i = 0; i < 8; i++)
        #pragma unroll
        for (int j = 0; j < 8; j++) acc[i][j] = 0.f;

    for (int k0 = 0; k0 < K; k0 += 8) {
        #pragma unroll
        for (int i = 0; i < 4; i++) {
            int e   = t + 256 * i;
            int row = e >> 3, kk = e & 7;
            float val = 0.f;
            if (m0 + row < M) val = A[(size_t)(m0 + row) * K + k0 + kk];
            As[kk][row] = val;
            int kw = e >> 7, n = e & 127;
            Ws[kw][n] = W[(size_t)(k0 + kw) * N + n0 + n];
        }
        __syncthreads();
        #pragma unroll
        for (int kk = 0; kk < 8; kk++) {
            float a[8], w[8];
            #pragma unroll
            for (int i = 0; i < 8; i++) a[i] = As[kk][ty * 8 + i];
            #pragma unroll
            for (int j = 0; j < 8; j++) w[j] = Ws[kk][tx * 8 + j];
            #pragma unroll
            for (int i = 0; i < 8; i++)
                #pragma unroll
                for (int j = 0; j < 8; j++)
                    acc[i][j] += a[i] * w[j];
        }
        __syncthreads();
    }
    #pragma unroll
    for (int i = 0; i < 8; i++) {
        int m = m0 + ty * 8 + i;
        if (m >= M) continue;
        #pragma unroll
        for (int j = 0; j < 8; j++) {
            int n = n0 + tx * 8 + j;
            float v = acc[i][j] + bias[n];
            if (skip) v += skip[(size_t)m * N + n];
            C[(size_t)m * N + n] = v;
        }
    }
}

// ---------------- RoPE (in-place on q,k halves of g_qkv) --------------------
__global__ void rope_kernel() {
    int idx = blockIdx.x * blockDim.x + threadIdx.x;
    const int total = 2 * NB * NH * SEQ * 24;
    if (idx >= total) return;
    int j = idx % 24; idx /= 24;
    int s = idx % SEQ; idx /= SEQ;
    int h = idx % NH; idx /= NH;
    int b = idx % NB; idx /= NB;
    int which = idx;  // 0 = q, 1 = k

    // position
    float ph = 0.f, pw = 0.f, pr = 0.f;
    if (s > 0) {
        int b5, n, start;
        if      (s < 5)   { b5 = 0; n = 2;  start = 1;   }
        else if (s < 21)  { b5 = 1; n = 4;  start = 5;   }
        else if (s < 85)  { b5 = 2; n = 8;  start = 21;  }
        else if (s < 341) { b5 = 3; n = 16; start = 85;  }
        else              { b5 = 4; n = 32; start = 341; }
        int li = s - start;
        int r  = li / n, c = li % n;
        ph = -1.0f + (float)(2 * r + 1) / (float)n;
        pw = -1.0f + (float)(2 * c + 1) / (float)n;
        pr = (float)(b5 + 1) / 5.0f;
    }
    int comp = j >> 3;                 // 0:h, 1:w, 2:r
    int f    = j & 7;
    float p  = (comp == 0) ? ph : ((comp == 1) ? pw : pr);
    int kidx = f * 16 + h;             // freqs.reshape(8,16).T
    // freq = pi * exp(kidx * ln(10)/128) = pi * 2^(kidx*log2(10)/128)
    float freq  = (float)CUDART_PI_F * exp2f((float)kidx * (3.3219280948873623f / 128.0f));
    float theta = p * freq;
    float cs = cosf(theta), sn = sinf(theta);

    float* base = g_qkv + ((size_t)(b * SEQ + s)) * 3072 + which * 1024 + h * 64;
    float x1 = base[j], x2 = base[j + 24];
    base[j]      = x1 * cs - x2 * sn;
    base[j + 24] = x2 * cs + x1 * sn;
}

// ---------------- block-causal flash attention (fp32) -----------------------
__global__ __launch_bounds__(128)
void attn_kernel() {
    __shared__ float Ks[32][64];
    __shared__ float Vs[32][64];
    int qt = blockIdx.x;            // query tile of 128
    int h  = blockIdx.y;
    int b  = blockIdx.z;
    int t  = threadIdx.x;
    int s  = qt * 128 + t;
    bool valid = s < SEQ;
    int klim = valid ? block_end(s) : 0;
    int s_last = min(qt * 128 + 127, SEQ - 1);
    int kmax = block_end(s_last);

    const float4* qp = (const float4*)(g_qkv + ((size_t)(b * SEQ + min(s, SEQ - 1))) * 3072 + h * 64);
    float4 q[16];
    #pragma unroll
    for (int i = 0; i < 16; i++) {
        q[i] = qp[i];
        q[i].x *= 0.125f; q[i].y *= 0.125f; q[i].z *= 0.125f; q[i].w *= 0.125f;
    }
    float4 o[16];
    #pragma unroll
    for (int i = 0; i < 16; i++) o[i] = make_float4(0.f, 0.f, 0.f, 0.f);
    float m = -CUDART_INF_F, l = 0.f;

    int tl   = t >> 2;   // key row this thread loads
    int quad = t & 3;    // 16-float chunk of d

    for (int kt = 0; kt < kmax; kt += 32) {
        int tg = kt + tl;
        {
            const float4* kp = (const float4*)(g_qkv + ((size_t)(b * SEQ + min(tg, SEQ - 1))) * 3072 + 1024 + h * 64 + quad * 16);
            const float4* vp = kp + (1024 / 4);
            float4* kd = (float4*)&Ks[tl][quad * 16];
            float4* vd = (float4*)&Vs[tl][quad * 16];
            if (tg < kmax) {
                #pragma unroll
                for (int i = 0; i < 4; i++) { kd[i] = kp[i]; vd[i] = vp[i]; }
            } else {
                #pragma unroll
                for (int i = 0; i < 4; i++) { kd[i] = make_float4(0,0,0,0); vd[i] = make_float4(0,0,0,0); }
            }
        }
        __syncthreads();

        float sc[32];
        #pragma unroll 4
        for (int kk = 0; kk < 32; kk++) {
            const float4* kr = (const float4*)Ks[kk];
            float ax = 0.f, ay = 0.f, az = 0.f, aw = 0.f;
            #pragma unroll
            for (int i = 0; i < 16; i++) {
                float4 kv = kr[i];
                ax += q[i].x * kv.x; ay += q[i].y * kv.y;
                az += q[i].z * kv.z; aw += q[i].w * kv.w;
            }
            sc[kk] = (ax + ay) + (az + aw);
        }

        float mt = m;
        #pragma unroll
        for (int kk = 0; kk < 32; kk++)
            if (kt + kk < klim) mt = fmaxf(mt, sc[kk]);
        float corr = expf(m - mt);
        l *= corr;
        #pragma unroll
        for (int i = 0; i < 16; i++) {
            o[i].x *= corr; o[i].y *= corr; o[i].z *= corr; o[i].w *= corr;
        }
        #pragma unroll 4
        for (int kk = 0; kk < 32; kk++) {
            float p = (kt + kk < klim) ? expf(sc[kk] - mt) : 0.f;
            l += p;
            const float4* vr = (const float4*)Vs[kk];
            #pragma unroll
            for (int i = 0; i < 16; i++) {
                float4 vv = vr[i];
                o[i].x += p * vv.x; o[i].y += p * vv.y;
                o[i].z += p * vv.z; o[i].w += p * vv.w;
            }
        }
        m = mt;
        __syncthreads();
    }

    if (valid) {
        float inv = 1.0f / l;
        float4* op = (float4*)(g_oa + ((size_t)(b * SEQ + s)) * 1024 + h * 64);
        #pragma unroll
        for (int i = 0; i < 16; i++) {
            float4 r = o[i];
            r.x *= inv; r.y *= inv; r.z *= inv; r.w *= inv;
            op[i] = r;
        }
    }
}

// ---------------- launch ----------------------------------------------------
extern "C" void kernel_launch(void* const* d_in, const int* in_sizes, int n_in,
                              void* d_out, int out_size) {
    const float* x       = (const float*)d_in[0];
    const float* cond    = (const float*)d_in[1];
    const float* adaln_w = (const float*)d_in[2];
    const float* adaln_b = (const float*)d_in[3];
    const float* qkv_w   = (const float*)d_in[4];
    const float* qkv_b   = (const float*)d_in[5];
    const float* out_w   = (const float*)d_in[6];
    const float* out_b   = (const float*)d_in[7];
    float* out = (float*)d_out;

    void *p_xn, *p_qkv, *p_oa;
    cudaGetSymbolAddress(&p_xn,  g_xn);
    cudaGetSymbolAddress(&p_qkv, g_qkv);
    cudaGetSymbolAddress(&p_oa,  g_oa);
    float* xn  = (float*)p_xn;
    float* qkv = (float*)p_qkv;
    float* oa  = (float*)p_oa;

    adaln_kernel<<<NB, 256>>>(cond, adaln_w, adaln_b);
    ln_kernel<<<MROWS, 256>>>(x);

    {   // qkv = xn @ qkv_w + qkv_b
        dim3 g(3 * DIMD / 128, (MROWS + 127) / 128);
        gemm_kernel<<<g, 256>>>(xn, qkv_w, qkv_b, nullptr, qkv, MROWS, 3 * DIMD, DIMD);
    }
    {   // RoPE on q,k
        int total = 2 * NB * NH * SEQ * 24;
        rope_kernel<<<(total + 255) / 256, 256>>>();
    }
    {   // attention
        dim3 g((SEQ + 127) / 128, NH, NB);
        attn_kernel<<<g, 128>>>();
    }
    {   // out = oa @ out_w + out_b + x
        dim3 g(DIMD / 128, (MROWS + 127) / 128);
        gemm_kernel<<<g, 256>>>(oa, out_w, out_b, x, out, MROWS, DIMD, DIMD);
    }
}

// round 2
// speedup vs baseline: 1.4996x; 1.4996x over previous
#include <cuda_runtime.h>
#include <math.h>
#include <math_constants.h>
#include <stdint.h>

#define SEQ   1365
#define DIMD  1024
#define NH    16
#define HD    64
#define NB    8
#define MROWS (NB*SEQ)   // 10920

// ---------------- scratch (device globals: no allocations allowed) ----------
__device__ float g_wb [NB * 2 * DIMD];
__device__ float g_xn [ (size_t)MROWS * DIMD ];
__device__ float g_qkv[ (size_t)MROWS * 3 * DIMD ];
__device__ float g_oa [ (size_t)MROWS * DIMD ];

// ---------------- helpers ---------------------------------------------------
__device__ __forceinline__ int block_end(int s) {
    if (s < 1)   return 1;
    if (s < 5)   return 5;
    if (s < 21)  return 21;
    if (s < 85)  return 85;
    if (s < 341) return 341;
    return 1365;
}

__device__ __forceinline__ uint32_t f2tf32(float x) {
    uint32_t r;
    asm("cvt.rna.tf32.f32 %0, %1;" : "=r"(r) : "f"(x));
    return r;
}

__device__ __forceinline__ void mma_tf32(float* c, const uint32_t* a, const uint32_t* b) {
    asm volatile(
        "mma.sync.aligned.m16n8k8.row.col.f32.tf32.tf32.f32 "
        "{%0,%1,%2,%3}, {%4,%5,%6,%7}, {%8,%9}, {%0,%1,%2,%3};"
        : "+f"(c[0]), "+f"(c[1]), "+f"(c[2]), "+f"(c[3])
        : "r"(a[0]), "r"(a[1]), "r"(a[2]), "r"(a[3]), "r"(b[0]), "r"(b[1]));
}

__device__ __forceinline__ void cp16(void* s, const void* g) {
    uint32_t sa = (uint32_t)__cvta_generic_to_shared(s);
    asm volatile("cp.async.cg.shared.global [%0], [%1], 16;\n" :: "r"(sa), "l"(g));
}
__device__ __forceinline__ void cp_commit() { asm volatile("cp.async.commit_group;\n"); }
template <int N>
__device__ __forceinline__ void cp_wait() { asm volatile("cp.async.wait_group %0;\n" :: "n"(N)); }

// ---------------- adaLN -----------------------------------------------------
__global__ void adaln_kernel(const float* __restrict__ cond,
                             const float* __restrict__ w,
                             const float* __restrict__ bias) {
    __shared__ float c[256];
    int b = blockIdx.x;
    int t = threadIdx.x;
    c[t] = cond[b * 256 + t];
    __syncthreads();
    for (int j = t; j < 2048; j += 256) {
        float acc = bias[j];
        #pragma unroll 8
        for (int k = 0; k < 256; k++) acc += c[k] * w[k * 2048 + j];
        g_wb[b * 2048 + j] = acc;
    }
}

// ---------------- LayerNorm + modulate --------------------------------------
__global__ void ln_kernel(const float* __restrict__ x) {
    int row = blockIdx.x;
    int b   = row / SEQ;
    int t   = threadIdx.x;
    const float4* xr = (const float4*)(x + (size_t)row * DIMD);
    float4 v = xr[t];
    float s  = v.x + v.y + v.z + v.w;
    float ss = v.x*v.x + v.y*v.y + v.z*v.z + v.w*v.w;
    #pragma unroll
    for (int o = 16; o > 0; o >>= 1) {
        s  += __shfl_down_sync(0xffffffffu, s,  o);
        ss += __shfl_down_sync(0xffffffffu, ss, o);
    }
    __shared__ float sh_s[8], sh_ss[8];
    int w = t >> 5, ln = t & 31;
    if (ln == 0) { sh_s[w] = s; sh_ss[w] = ss; }
    __syncthreads();
    if (w == 0) {
        s  = (ln < 8) ? sh_s[ln]  : 0.f;
        ss = (ln < 8) ? sh_ss[ln] : 0.f;
        #pragma unroll
        for (int o = 4; o > 0; o >>= 1) {
            s  += __shfl_down_sync(0xffffffffu, s,  o);
            ss += __shfl_down_sync(0xffffffffu, ss, o);
        }
        if (ln == 0) { sh_s[0] = s; sh_ss[0] = ss; }
    }
    __syncthreads();
    float mu   = sh_s[0]  * (1.0f / 1024.0f);
    float var  = sh_ss[0] * (1.0f / 1024.0f) - mu * mu;
    float rstd = rsqrtf(var + 1e-5f);
    const float4* wr = (const float4*)(g_wb + b * 2048);
    float4 wv = wr[t];
    float4 bv = wr[256 + t];
    float4 r;
    r.x = (v.x - mu) * rstd * (wv.x + 1.0f) + bv.x;
    r.y = (v.y - mu) * rstd * (wv.y + 1.0f) + bv.y;
    r.z = (v.z - mu) * rstd * (wv.z + 1.0f) + bv.z;
    r.w = (v.w - mu) * rstd * (wv.w + 1.0f) + bv.w;
    ((float4*)(g_xn + (size_t)row * DIMD))[t] = r;
}

// ---------------- tf32 tensor-core GEMM: C = A@W + bias (+skip) -------------
// 128x128 tile, BK=32, 256 threads (8 warps, 2x4), warp tile 64x32,
// mma.sync m16n8k8 tf32, cp.async double buffering.
#define ASTRIDE 36
#define BSTRIDE 136
#define AS(buf,m,k) sA[(buf)*128*ASTRIDE + (m)*ASTRIDE + (k)]
#define BS(buf,k,n) sB[(buf)*32*BSTRIDE + (k)*BSTRIDE + (n)]

__global__ __launch_bounds__(256)
void gemm_tf32(const float* __restrict__ A, const float* __restrict__ W,
               const float* __restrict__ bias, const float* __restrict__ skip,
               float* __restrict__ C, int M, int N, int K) {
    extern __shared__ float smem[];
    float* sA = smem;                      // 2*128*36 floats
    float* sB = smem + 2 * 128 * ASTRIDE;  // 2*32*136 floats

    const int t    = threadIdx.x;
    const int lane = t & 31;
    const int w    = t >> 5;
    const int wm   = (w >> 2) * 64;   // 0 / 64
    const int wn   = (w & 3) * 32;    // 0/32/64/96
    const int m0   = blockIdx.y * 128;
    const int n0   = blockIdx.x * 128;

    float acc[16][4];
    #pragma unroll
    for (int i = 0; i < 16; i++)
        #pragma unroll
        for (int j = 0; j < 4; j++) acc[i][j] = 0.f;

    const int NT = K / 32;

    // tile loader
    auto load_tile = [&](int kt, int buf) {
        int k0 = kt * 32;
        #pragma unroll
        for (int i = 0; i < 4; i++) {
            int idx = t + 256 * i;
            // A: 128 rows x 8 float4
            int row = idx >> 3, seg = idx & 7;
            int gm  = min(m0 + row, M - 1);
            cp16(&AS(buf, row, seg * 4), &A[(size_t)gm * K + k0 + seg * 4]);
            // B: 32 rows x 32 float4
            int krow = idx >> 5, nseg = idx & 31;
            cp16(&BS(buf, krow, nseg * 4), &W[(size_t)(k0 + krow) * N + n0 + nseg * 4]);
        }
    };

    load_tile(0, 0);
    cp_commit();

    for (int kt = 0; kt < NT; kt++) {
        int buf = kt & 1;
        if (kt + 1 < NT) {
            load_tile(kt + 1, buf ^ 1);
            cp_commit();
            cp_wait<1>();
        } else {
            cp_wait<0>();
        }
        __syncthreads();

        #pragma unroll
        for (int ks = 0; ks < 4; ks++) {
            uint32_t a[4][4], b[4][2];
            #pragma unroll
            for (int mt = 0; mt < 4; mt++) {
                int r0 = wm + mt * 16 + (lane >> 2);
                int c0 = ks * 8 + (lane & 3);
                a[mt][0] = f2tf32(AS(buf, r0,     c0));
                a[mt][1] = f2tf32(AS(buf, r0 + 8, c0));
                a[mt][2] = f2tf32(AS(buf, r0,     c0 + 4));
                a[mt][3] = f2tf32(AS(buf, r0 + 8, c0 + 4));
            }
            #pragma unroll
            for (int nt = 0; nt < 4; nt++) {
                int kb = ks * 8 + (lane & 3);
                int nb = wn + nt * 8 + (lane >> 2);
                b[nt][0] = f2tf32(BS(buf, kb,     nb));
                b[nt][1] = f2tf32(BS(buf, kb + 4, nb));
            }
            #pragma unroll
            for (int mt = 0; mt < 4; mt++)
                #pragma unroll
                for (int nt = 0; nt < 4; nt++)
                    mma_tf32(acc[mt * 4 + nt], a[mt], b[nt]);
        }
        __syncthreads();
    }

    // epilogue
    #pragma unroll
    for (int mt = 0; mt < 4; mt++) {
        #pragma unroll
        for (int nt = 0; nt < 4; nt++) {
            float* cc = acc[mt * 4 + nt];
            int r  = m0 + wm + mt * 16 + (lane >> 2);
            int cb = n0 + wn + nt * 8 + 2 * (lane & 3);
            float b0 = bias[cb], b1 = bias[cb + 1];
            if (r < M) {
                float v0 = cc[0] + b0, v1 = cc[1] + b1;
                if (skip) {
                    v0 += skip[(size_t)r * N + cb];
                    v1 += skip[(size_t)r * N + cb + 1];
                }
                C[(size_t)r * N + cb]     = v0;
                C[(size_t)r * N + cb + 1] = v1;
            }
            if (r + 8 < M) {
                float v2 = cc[2] + b0, v3 = cc[3] + b1;
                if (skip) {
                    v2 += skip[(size_t)(r + 8) * N + cb];
                    v3 += skip[(size_t)(r + 8) * N + cb + 1];
                }
                C[(size_t)(r + 8) * N + cb]     = v2;
                C[(size_t)(r + 8) * N + cb + 1] = v3;
            }
        }
    }
}

// ---------------- RoPE ------------------------------------------------------
__global__ void rope_kernel() {
    int idx = blockIdx.x * blockDim.x + threadIdx.x;
    const int total = 2 * NB * NH * SEQ * 24;
    if (idx >= total) return;
    int j = idx % 24; idx /= 24;
    int s = idx % SEQ; idx /= SEQ;
    int h = idx % NH; idx /= NH;
    int b = idx % NB; idx /= NB;
    int which = idx;

    float ph = 0.f, pw = 0.f, pr = 0.f;
    if (s > 0) {
        int b5, n, start;
        if      (s < 5)   { b5 = 0; n = 2;  start = 1;   }
        else if (s < 21)  { b5 = 1; n = 4;  start = 5;   }
        else if (s < 85)  { b5 = 2; n = 8;  start = 21;  }
        else if (s < 341) { b5 = 3; n = 16; start = 85;  }
        else              { b5 = 4; n = 32; start = 341; }
        int li = s - start;
        int r  = li / n, c = li % n;
        ph = -1.0f + (float)(2 * r + 1) / (float)n;
        pw = -1.0f + (float)(2 * c + 1) / (float)n;
        pr = (float)(b5 + 1) / 5.0f;
    }
    int comp = j >> 3;
    int f    = j & 7;
    float p  = (comp == 0) ? ph : ((comp == 1) ? pw : pr);
    int kidx = f * 16 + h;
    float freq  = (float)CUDART_PI_F * exp2f((float)kidx * (3.3219280948873623f / 128.0f));
    float theta = p * freq;
    float cs = cosf(theta), sn = sinf(theta);

    float* base = g_qkv + ((size_t)(b * SEQ + s)) * 3072 + which * 1024 + h * 64;
    float x1 = base[j], x2 = base[j + 24];
    base[j]      = x1 * cs - x2 * sn;
    base[j + 24] = x2 * cs + x1 * sn;
}

// ---------------- block-causal flash attention (fp32 SIMT) ------------------
__global__ __launch_bounds__(128)
void attn_kernel() {
    __shared__ float Ks[32][64];
    __shared__ float Vs[32][64];
    int qt = blockIdx.x;
    int h  = blockIdx.y;
    int b  = blockIdx.z;
    int t  = threadIdx.x;
    int s  = qt * 128 + t;
    bool valid = s < SEQ;
    int klim = valid ? block_end(s) : 0;
    int s_last = min(qt * 128 + 127, SEQ - 1);
    int kmax = block_end(s_last);

    const float4* qp = (const float4*)(g_qkv + ((size_t)(b * SEQ + min(s, SEQ - 1))) * 3072 + h * 64);
    float4 q[16];
    #pragma unroll
    for (int i = 0; i < 16; i++) {
        q[i] = qp[i];
        q[i].x *= 0.125f; q[i].y *= 0.125f; q[i].z *= 0.125f; q[i].w *= 0.125f;
    }
    float4 o[16];
    #pragma unroll
    for (int i = 0; i < 16; i++) o[i] = make_float4(0.f, 0.f, 0.f, 0.f);
    float m = -CUDART_INF_F, l = 0.f;

    int tl   = t >> 2;
    int quad = t & 3;

    for (int kt = 0; kt < kmax; kt += 32) {
        int tg = kt + tl;
        {
            const float4* kp = (const float4*)(g_qkv + ((size_t)(b * SEQ + min(tg, SEQ - 1))) * 3072 + 1024 + h * 64 + quad * 16);
            const float4* vp = kp + (1024 / 4);
            float4* kd = (float4*)&Ks[tl][quad * 16];
            float4* vd = (float4*)&Vs[tl][quad * 16];
            if (tg < kmax) {
                #pragma unroll
                for (int i = 0; i < 4; i++) { kd[i] = kp[i]; vd[i] = vp[i]; }
            } else {
                #pragma unroll
                for (int i = 0; i < 4; i++) { kd[i] = make_float4(0,0,0,0); vd[i] = make_float4(0,0,0,0); }
            }
        }
        __syncthreads();

        float sc[32];
        #pragma unroll 4
        for (int kk = 0; kk < 32; kk++) {
            const float4* kr = (const float4*)Ks[kk];
            float ax = 0.f, ay = 0.f, az = 0.f, aw = 0.f;
            #pragma unroll
            for (int i = 0; i < 16; i++) {
                float4 kv = kr[i];
                ax += q[i].x * kv.x; ay += q[i].y * kv.y;
                az += q[i].z * kv.z; aw += q[i].w * kv.w;
            }
            sc[kk] = (ax + ay) + (az + aw);
        }

        float mt = m;
        #pragma unroll
        for (int kk = 0; kk < 32; kk++)
            if (kt + kk < klim) mt = fmaxf(mt, sc[kk]);
        float corr = expf(m - mt);
        l *= corr;
        #pragma unroll
        for (int i = 0; i < 16; i++) {
            o[i].x *= corr; o[i].y *= corr; o[i].z *= corr; o[i].w *= corr;
        }
        #pragma unroll 4
        for (int kk = 0; kk < 32; kk++) {
            float p = (kt + kk < klim) ? expf(sc[kk] - mt) : 0.f;
            l += p;
            const float4* vr = (const float4*)Vs[kk];
            #pragma unroll
            for (int i = 0; i < 16; i++) {
                float4 vv = vr[i];
                o[i].x += p * vv.x; o[i].y += p * vv.y;
                o[i].z += p * vv.z; o[i].w += p * vv.w;
            }
        }
        m = mt;
        __syncthreads();
    }

    if (valid) {
        float inv = 1.0f / l;
        float4* op = (float4*)(g_oa + ((size_t)(b * SEQ + s)) * 1024 + h * 64);
        #pragma unroll
        for (int i = 0; i < 16; i++) {
            float4 r = o[i];
            r.x *= inv; r.y *= inv; r.z *= inv; r.w *= inv;
            op[i] = r;
        }
    }
}

// ---------------- launch ----------------------------------------------------
extern "C" void kernel_launch(void* const* d_in, const int* in_sizes, int n_in,
                              void* d_out, int out_size) {
    const float* x       = (const float*)d_in[0];
    const float* cond    = (const float*)d_in[1];
    const float* adaln_w = (const float*)d_in[2];
    const float* adaln_b = (const float*)d_in[3];
    const float* qkv_w   = (const float*)d_in[4];
    const float* qkv_b   = (const float*)d_in[5];
    const float* out_w   = (const float*)d_in[6];
    const float* out_b   = (const float*)d_in[7];
    float* out = (float*)d_out;

    void *p_xn, *p_qkv, *p_oa;
    cudaGetSymbolAddress(&p_xn,  g_xn);
    cudaGetSymbolAddress(&p_qkv, g_qkv);
    cudaGetSymbolAddress(&p_oa,  g_oa);
    float* xn  = (float*)p_xn;
    float* qkv = (float*)p_qkv;
    float* oa  = (float*)p_oa;

    const int smem_bytes = (2 * 128 * ASTRIDE + 2 * 32 * BSTRIDE) * 4;  // 71680
    cudaFuncSetAttribute(gemm_tf32, cudaFuncAttributeMaxDynamicSharedMemorySize, smem_bytes);

    adaln_kernel<<<NB, 256>>>(cond, adaln_w, adaln_b);
    ln_kernel<<<MROWS, 256>>>(x);

    {   // qkv = xn @ qkv_w + qkv_b
        dim3 g(3 * DIMD / 128, (MROWS + 127) / 128);
        gemm_tf32<<<g, 256, smem_bytes>>>(xn, qkv_w, qkv_b, nullptr, qkv, MROWS, 3 * DIMD, DIMD);
    }
    {   // RoPE
        int total = 2 * NB * NH * SEQ * 24;
        rope_kernel<<<(total + 255) / 256, 256>>>();
    }
    {   // attention
        dim3 g((SEQ + 127) / 128, NH, NB);
        attn_kernel<<<g, 128>>>();
    }
    {   // out = oa @ out_w + out_b + x
        dim3 g(DIMD / 128, (MROWS + 127) / 128);
        gemm_tf32<<<g, 256, smem_bytes>>>(oa, out_w, out_b, x, out, MROWS, DIMD, DIMD);
    }
}

// round 3
// speedup vs baseline: 2.9409x; 1.9612x over previous
#include <cuda_runtime.h>
#include <math.h>
#include <math_constants.h>
#include <stdint.h>

#define SEQ   1365
#define DIMD  1024
#define NH    16
#define HD    64
#define NB    8
#define MROWS (NB*SEQ)   // 10920

// ---------------- scratch ----------------------------------------------------
__device__ float g_wb [NB * 2 * DIMD];
__device__ float g_xn [ (size_t)MROWS * DIMD ];
__device__ float g_qkv[ (size_t)MROWS * 3 * DIMD ];
__device__ float g_oa [ (size_t)MROWS * DIMD ];

// ---------------- helpers ----------------------------------------------------
__device__ __forceinline__ int block_end(int s) {
    if (s < 1)   return 1;
    if (s < 5)   return 5;
    if (s < 21)  return 21;
    if (s < 85)  return 85;
    if (s < 341) return 341;
    return 1365;
}

__device__ __forceinline__ uint32_t f2tf32(float x) {
    uint32_t r;
    asm("cvt.rna.tf32.f32 %0, %1;" : "=r"(r) : "f"(x));
    return r;
}

__device__ __forceinline__ void mma_tf32(float* c, const uint32_t* a, const uint32_t* b) {
    asm volatile(
        "mma.sync.aligned.m16n8k8.row.col.f32.tf32.tf32.f32 "
        "{%0,%1,%2,%3}, {%4,%5,%6,%7}, {%8,%9}, {%0,%1,%2,%3};"
        : "+f"(c[0]), "+f"(c[1]), "+f"(c[2]), "+f"(c[3])
        : "r"(a[0]), "r"(a[1]), "r"(a[2]), "r"(a[3]), "r"(b[0]), "r"(b[1]));
}

__device__ __forceinline__ void cp16(void* s, const void* g) {
    uint32_t sa = (uint32_t)__cvta_generic_to_shared(s);
    asm volatile("cp.async.cg.shared.global [%0], [%1], 16;\n" :: "r"(sa), "l"(g));
}
__device__ __forceinline__ void cp_commit() { asm volatile("cp.async.commit_group;\n"); }
template <int N>
__device__ __forceinline__ void cp_wait() { asm volatile("cp.async.wait_group %0;\n" :: "n"(N)); }

// ---------------- adaLN ------------------------------------------------------
__global__ void adaln_kernel(const float* __restrict__ cond,
                             const float* __restrict__ w,
                             const float* __restrict__ bias) {
    __shared__ float c[256];
    int b = blockIdx.x;
    int t = threadIdx.x;
    c[t] = cond[b * 256 + t];
    __syncthreads();
    for (int j = t; j < 2048; j += 256) {
        float acc = bias[j];
        #pragma unroll 8
        for (int k = 0; k < 256; k++) acc += c[k] * w[k * 2048 + j];
        g_wb[b * 2048 + j] = acc;
    }
}

// ---------------- LayerNorm + modulate ---------------------------------------
__global__ void ln_kernel(const float* __restrict__ x) {
    int row = blockIdx.x;
    int b   = row / SEQ;
    int t   = threadIdx.x;
    const float4* xr = (const float4*)(x + (size_t)row * DIMD);
    float4 v = xr[t];
    float s  = v.x + v.y + v.z + v.w;
    float ss = v.x*v.x + v.y*v.y + v.z*v.z + v.w*v.w;
    #pragma unroll
    for (int o = 16; o > 0; o >>= 1) {
        s  += __shfl_down_sync(0xffffffffu, s,  o);
        ss += __shfl_down_sync(0xffffffffu, ss, o);
    }
    __shared__ float sh_s[8], sh_ss[8];
    int w = t >> 5, ln = t & 31;
    if (ln == 0) { sh_s[w] = s; sh_ss[w] = ss; }
    __syncthreads();
    if (w == 0) {
        s  = (ln < 8) ? sh_s[ln]  : 0.f;
        ss = (ln < 8) ? sh_ss[ln] : 0.f;
        #pragma unroll
        for (int o = 4; o > 0; o >>= 1) {
            s  += __shfl_down_sync(0xffffffffu, s,  o);
            ss += __shfl_down_sync(0xffffffffu, ss, o);
        }
        if (ln == 0) { sh_s[0] = s; sh_ss[0] = ss; }
    }
    __syncthreads();
    float mu   = sh_s[0]  * (1.0f / 1024.0f);
    float var  = sh_ss[0] * (1.0f / 1024.0f) - mu * mu;
    float rstd = rsqrtf(var + 1e-5f);
    const float4* wr = (const float4*)(g_wb + b * 2048);
    float4 wv = wr[t];
    float4 bv = wr[256 + t];
    float4 r;
    r.x = (v.x - mu) * rstd * (wv.x + 1.0f) + bv.x;
    r.y = (v.y - mu) * rstd * (wv.y + 1.0f) + bv.y;
    r.z = (v.z - mu) * rstd * (wv.z + 1.0f) + bv.z;
    r.w = (v.w - mu) * rstd * (wv.w + 1.0f) + bv.w;
    ((float4*)(g_xn + (size_t)row * DIMD))[t] = r;
}

// ---------------- tf32 GEMM --------------------------------------------------
#define ASTRIDE 36
#define BSTRIDE 136
#define AS(buf,m,k) sA[(buf)*128*ASTRIDE + (m)*ASTRIDE + (k)]
#define BS(buf,k,n) sB[(buf)*32*BSTRIDE + (k)*BSTRIDE + (n)]

__global__ __launch_bounds__(256)
void gemm_tf32(const float* __restrict__ A, const float* __restrict__ W,
               const float* __restrict__ bias, const float* __restrict__ skip,
               float* __restrict__ C, int M, int N, int K) {
    extern __shared__ float smem[];
    float* sA = smem;
    float* sB = smem + 2 * 128 * ASTRIDE;

    const int t    = threadIdx.x;
    const int lane = t & 31;
    const int w    = t >> 5;
    const int wm   = (w >> 2) * 64;
    const int wn   = (w & 3) * 32;
    const int m0   = blockIdx.y * 128;
    const int n0   = blockIdx.x * 128;

    float acc[16][4];
    #pragma unroll
    for (int i = 0; i < 16; i++)
        #pragma unroll
        for (int j = 0; j < 4; j++) acc[i][j] = 0.f;

    const int NT = K / 32;

    auto load_tile = [&](int kt, int buf) {
        int k0 = kt * 32;
        #pragma unroll
        for (int i = 0; i < 4; i++) {
            int idx = t + 256 * i;
            int row = idx >> 3, seg = idx & 7;
            int gm  = min(m0 + row, M - 1);
            cp16(&AS(buf, row, seg * 4), &A[(size_t)gm * K + k0 + seg * 4]);
            int krow = idx >> 5, nseg = idx & 31;
            cp16(&BS(buf, krow, nseg * 4), &W[(size_t)(k0 + krow) * N + n0 + nseg * 4]);
        }
    };

    load_tile(0, 0);
    cp_commit();

    for (int kt = 0; kt < NT; kt++) {
        int buf = kt & 1;
        if (kt + 1 < NT) {
            load_tile(kt + 1, buf ^ 1);
            cp_commit();
            cp_wait<1>();
        } else {
            cp_wait<0>();
        }
        __syncthreads();

        #pragma unroll
        for (int ks = 0; ks < 4; ks++) {
            uint32_t a[4][4], b[4][2];
            #pragma unroll
            for (int mt = 0; mt < 4; mt++) {
                int r0 = wm + mt * 16 + (lane >> 2);
                int c0 = ks * 8 + (lane & 3);
                a[mt][0] = f2tf32(AS(buf, r0,     c0));
                a[mt][1] = f2tf32(AS(buf, r0 + 8, c0));
                a[mt][2] = f2tf32(AS(buf, r0,     c0 + 4));
                a[mt][3] = f2tf32(AS(buf, r0 + 8, c0 + 4));
            }
            #pragma unroll
            for (int nt = 0; nt < 4; nt++) {
                int kb = ks * 8 + (lane & 3);
                int nb = wn + nt * 8 + (lane >> 2);
                b[nt][0] = f2tf32(BS(buf, kb,     nb));
                b[nt][1] = f2tf32(BS(buf, kb + 4, nb));
            }
            #pragma unroll
            for (int mt = 0; mt < 4; mt++)
                #pragma unroll
                for (int nt = 0; nt < 4; nt++)
                    mma_tf32(acc[mt * 4 + nt], a[mt], b[nt]);
        }
        __syncthreads();
    }

    #pragma unroll
    for (int mt = 0; mt < 4; mt++) {
        #pragma unroll
        for (int nt = 0; nt < 4; nt++) {
            float* cc = acc[mt * 4 + nt];
            int r  = m0 + wm + mt * 16 + (lane >> 2);
            int cb = n0 + wn + nt * 8 + 2 * (lane & 3);
            float b0 = bias[cb], b1 = bias[cb + 1];
            if (r < M) {
                float v0 = cc[0] + b0, v1 = cc[1] + b1;
                if (skip) {
                    v0 += skip[(size_t)r * N + cb];
                    v1 += skip[(size_t)r * N + cb + 1];
                }
                C[(size_t)r * N + cb]     = v0;
                C[(size_t)r * N + cb + 1] = v1;
            }
            if (r + 8 < M) {
                float v2 = cc[2] + b0, v3 = cc[3] + b1;
                if (skip) {
                    v2 += skip[(size_t)(r + 8) * N + cb];
                    v3 += skip[(size_t)(r + 8) * N + cb + 1];
                }
                C[(size_t)(r + 8) * N + cb]     = v2;
                C[(size_t)(r + 8) * N + cb + 1] = v3;
            }
        }
    }
}

// ---------------- RoPE -------------------------------------------------------
__global__ void rope_kernel() {
    int idx = blockIdx.x * blockDim.x + threadIdx.x;
    const int total = 2 * NB * NH * SEQ * 24;
    if (idx >= total) return;
    int j = idx % 24; idx /= 24;
    int s = idx % SEQ; idx /= SEQ;
    int h = idx % NH; idx /= NH;
    int b = idx % NB; idx /= NB;
    int which = idx;

    float ph = 0.f, pw = 0.f, pr = 0.f;
    if (s > 0) {
        int b5, n, start;
        if      (s < 5)   { b5 = 0; n = 2;  start = 1;   }
        else if (s < 21)  { b5 = 1; n = 4;  start = 5;   }
        else if (s < 85)  { b5 = 2; n = 8;  start = 21;  }
        else if (s < 341) { b5 = 3; n = 16; start = 85;  }
        else              { b5 = 4; n = 32; start = 341; }
        int li = s - start;
        int r  = li / n, c = li % n;
        ph = -1.0f + (float)(2 * r + 1) / (float)n;
        pw = -1.0f + (float)(2 * c + 1) / (float)n;
        pr = (float)(b5 + 1) / 5.0f;
    }
    int comp = j >> 3;
    int f    = j & 7;
    float p  = (comp == 0) ? ph : ((comp == 1) ? pw : pr);
    int kidx = f * 16 + h;
    float freq  = (float)CUDART_PI_F * exp2f((float)kidx * (3.3219280948873623f / 128.0f));
    float theta = p * freq;
    float cs = cosf(theta), sn = sinf(theta);

    float* base = g_qkv + ((size_t)(b * SEQ + s)) * 3072 + which * 1024 + h * 64;
    float x1 = base[j], x2 = base[j + 24];
    base[j]      = x1 * cs - x2 * sn;
    base[j + 24] = x2 * cs + x1 * sn;
}

// ---------------- tensor-core block-causal flash attention -------------------
// block: 128 queries x (b,h). 8 warps, each warp owns 16 rows.
// K/V tiles 64 keys in smem (cp.async double buffer, stride 68: conflict-free).
#define APAD 68

__global__ __launch_bounds__(256)
void attn_mma_kernel() {
    extern __shared__ float sm[];
    float* sK = sm;                    // 2 * 64 * APAD
    float* sV = sm + 2 * 64 * APAD;    // 2 * 64 * APAD

    const int t    = threadIdx.x;
    const int lane = t & 31;
    const int w    = t >> 5;
    const int qi   = lane & 3;
    const int gp   = lane >> 2;
    const int qt = blockIdx.x, h = blockIdx.y, b = blockIdx.z;
    const int q0 = qt * 128;
    const int rA = q0 + w * 16 + gp;
    const int rB = rA + 8;
    const int klimA = (rA < SEQ) ? block_end(rA) : 0;
    const int klimB = (rB < SEQ) ? block_end(rB) : 0;
    const int kmax  = block_end(min(q0 + 127, SEQ - 1));

    // Q fragments (pre-scaled by 1/sqrt(64))
    uint32_t qf[8][4];
    {
        const float* QA = g_qkv + ((size_t)(b * SEQ + min(rA, SEQ - 1))) * 3072 + h * 64;
        const float* QB = g_qkv + ((size_t)(b * SEQ + min(rB, SEQ - 1))) * 3072 + h * 64;
        #pragma unroll
        for (int ks = 0; ks < 8; ks++) {
            qf[ks][0] = f2tf32(QA[ks * 8 + qi]     * 0.125f);
            qf[ks][1] = f2tf32(QB[ks * 8 + qi]     * 0.125f);
            qf[ks][2] = f2tf32(QA[ks * 8 + qi + 4] * 0.125f);
            qf[ks][3] = f2tf32(QB[ks * 8 + qi + 4] * 0.125f);
        }
    }

    float o[8][4];
    #pragma unroll
    for (int i = 0; i < 8; i++)
        #pragma unroll
        for (int j = 0; j < 4; j++) o[i][j] = 0.f;
    float mA = -1e30f, mB = -1e30f, lA = 0.f, lB = 0.f;

    auto loadkv = [&](int kt_, int buf) {
        #pragma unroll
        for (int i = 0; i < 4; i++) {
            int idx = t + 256 * i;
            int key = idx >> 4, seg = idx & 15;
            int gk  = min(kt_ + key, SEQ - 1);
            const float* kp = g_qkv + ((size_t)(b * SEQ + gk)) * 3072 + 1024 + h * 64 + seg * 4;
            cp16(&sK[buf * 64 * APAD + key * APAD + seg * 4], kp);
            cp16(&sV[buf * 64 * APAD + key * APAD + seg * 4], kp + 1024);
        }
    };

    loadkv(0, 0);
    cp_commit();
    const int NIT = (kmax + 63) >> 6;

    for (int it = 0; it < NIT; it++) {
        const int kt_ = it * 64;
        const int buf = it & 1;
        if (it + 1 < NIT) {
            loadkv(kt_ + 64, buf ^ 1);
            cp_commit();
            cp_wait<1>();
        } else {
            cp_wait<0>();
        }
        __syncthreads();

        // S = Q @ K^T
        float sc[8][4];
        #pragma unroll
        for (int i = 0; i < 8; i++)
            #pragma unroll
            for (int j = 0; j < 4; j++) sc[i][j] = 0.f;
        const float* Kb = &sK[buf * 64 * APAD];
        #pragma unroll
        for (int ks = 0; ks < 8; ks++) {
            #pragma unroll
            for (int nt = 0; nt < 8; nt++) {
                uint32_t bf[2];
                const float* kp = &Kb[(nt * 8 + gp) * APAD + ks * 8 + qi];
                bf[0] = f2tf32(kp[0]);
                bf[1] = f2tf32(kp[4]);
                mma_tf32(sc[nt], qf[ks], bf);
            }
        }

        // mask + online softmax
        float nmA = mA, nmB = mB;
        #pragma unroll
        for (int nt = 0; nt < 8; nt++) {
            int c0 = kt_ + nt * 8 + 2 * qi;
            if (c0     >= klimA) sc[nt][0] = -1e30f;
            if (c0 + 1 >= klimA) sc[nt][1] = -1e30f;
            if (c0     >= klimB) sc[nt][2] = -1e30f;
            if (c0 + 1 >= klimB) sc[nt][3] = -1e30f;
            nmA = fmaxf(nmA, fmaxf(sc[nt][0], sc[nt][1]));
            nmB = fmaxf(nmB, fmaxf(sc[nt][2], sc[nt][3]));
        }
        nmA = fmaxf(nmA, __shfl_xor_sync(0xffffffffu, nmA, 1));
        nmA = fmaxf(nmA, __shfl_xor_sync(0xffffffffu, nmA, 2));
        nmB = fmaxf(nmB, __shfl_xor_sync(0xffffffffu, nmB, 1));
        nmB = fmaxf(nmB, __shfl_xor_sync(0xffffffffu, nmB, 2));
        float corrA = __expf(mA - nmA);
        float corrB = __expf(mB - nmB);
        mA = nmA; mB = nmB;
        lA *= corrA; lB *= corrB;
        #pragma unroll
        for (int nt = 0; nt < 8; nt++) {
            o[nt][0] *= corrA; o[nt][1] *= corrA;
            o[nt][2] *= corrB; o[nt][3] *= corrB;
        }
        #pragma unroll
        for (int nt = 0; nt < 8; nt++) {
            sc[nt][0] = __expf(sc[nt][0] - mA);
            sc[nt][1] = __expf(sc[nt][1] - mA);
            sc[nt][2] = __expf(sc[nt][2] - mB);
            sc[nt][3] = __expf(sc[nt][3] - mB);
            lA += sc[nt][0] + sc[nt][1];
            lB += sc[nt][2] + sc[nt][3];
        }

        // O += P @ V (transpose P fragments via intra-quad shuffles)
        const float* Vb = &sV[buf * 64 * APAD];
        const int s_lo = (lane & ~3) | (qi >> 1);
        const int s_hi = s_lo + 2;
        #pragma unroll
        for (int kb = 0; kb < 8; kb++) {
            float v00 = __shfl_sync(0xffffffffu, sc[kb][0], s_lo);
            float v01 = __shfl_sync(0xffffffffu, sc[kb][1], s_lo);
            float v10 = __shfl_sync(0xffffffffu, sc[kb][0], s_hi);
            float v11 = __shfl_sync(0xffffffffu, sc[kb][1], s_hi);
            float w00 = __shfl_sync(0xffffffffu, sc[kb][2], s_lo);
            float w01 = __shfl_sync(0xffffffffu, sc[kb][3], s_lo);
            float w10 = __shfl_sync(0xffffffffu, sc[kb][2], s_hi);
            float w11 = __shfl_sync(0xffffffffu, sc[kb][3], s_hi);
            uint32_t pa[4];
            pa[0] = f2tf32((qi & 1) ? v01 : v00);
            pa[1] = f2tf32((qi & 1) ? w01 : w00);
            pa[2] = f2tf32((qi & 1) ? v11 : v10);
            pa[3] = f2tf32((qi & 1) ? w11 : w10);
            #pragma unroll
            for (int nt = 0; nt < 8; nt++) {
                uint32_t bf[2];
                bf[0] = f2tf32(Vb[(kb * 8 + qi)     * APAD + nt * 8 + gp]);
                bf[1] = f2tf32(Vb[(kb * 8 + qi + 4) * APAD + nt * 8 + gp]);
                mma_tf32(o[nt], pa, bf);
            }
        }
        __syncthreads();
    }

    // final row sums + store
    lA += __shfl_xor_sync(0xffffffffu, lA, 1);
    lA += __shfl_xor_sync(0xffffffffu, lA, 2);
    lB += __shfl_xor_sync(0xffffffffu, lB, 1);
    lB += __shfl_xor_sync(0xffffffffu, lB, 2);
    float invA = 1.0f / lA, invB = 1.0f / lB;

    if (rA < SEQ) {
        float* dst = g_oa + ((size_t)(b * SEQ + rA)) * 1024 + h * 64;
        #pragma unroll
        for (int nt = 0; nt < 8; nt++) {
            float2 v = make_float2(o[nt][0] * invA, o[nt][1] * invA);
            *(float2*)(dst + nt * 8 + 2 * qi) = v;
        }
    }
    if (rB < SEQ) {
        float* dst = g_oa + ((size_t)(b * SEQ + rB)) * 1024 + h * 64;
        #pragma unroll
        for (int nt = 0; nt < 8; nt++) {
            float2 v = make_float2(o[nt][2] * invB, o[nt][3] * invB);
            *(float2*)(dst + nt * 8 + 2 * qi) = v;
        }
    }
}

// ---------------- launch -----------------------------------------------------
extern "C" void kernel_launch(void* const* d_in, const int* in_sizes, int n_in,
                              void* d_out, int out_size) {
    const float* x       = (const float*)d_in[0];
    const float* cond    = (const float*)d_in[1];
    const float* adaln_w = (const float*)d_in[2];
    const float* adaln_b = (const float*)d_in[3];
    const float* qkv_w   = (const float*)d_in[4];
    const float* qkv_b   = (const float*)d_in[5];
    const float* out_w   = (const float*)d_in[6];
    const float* out_b   = (const float*)d_in[7];
    float* out = (float*)d_out;

    void *p_xn, *p_qkv, *p_oa;
    cudaGetSymbolAddress(&p_xn,  g_xn);
    cudaGetSymbolAddress(&p_qkv, g_qkv);
    cudaGetSymbolAddress(&p_oa,  g_oa);
    float* xn  = (float*)p_xn;
    float* qkv = (float*)p_qkv;
    float* oa  = (float*)p_oa;

    const int gemm_smem = (2 * 128 * ASTRIDE + 2 * 32 * BSTRIDE) * 4;
    cudaFuncSetAttribute(gemm_tf32, cudaFuncAttributeMaxDynamicSharedMemorySize, gemm_smem);
    const int attn_smem = 4 * 64 * APAD * 4;  // 69632
    cudaFuncSetAttribute(attn_mma_kernel, cudaFuncAttributeMaxDynamicSharedMemorySize, attn_smem);

    adaln_kernel<<<NB, 256>>>(cond, adaln_w, adaln_b);
    ln_kernel<<<MROWS, 256>>>(x);

    {   // qkv = xn @ qkv_w + qkv_b
        dim3 g(3 * DIMD / 128, (MROWS + 127) / 128);
        gemm_tf32<<<g, 256, gemm_smem>>>(xn, qkv_w, qkv_b, nullptr, qkv, MROWS, 3 * DIMD, DIMD);
    }
    {   // RoPE
        int total = 2 * NB * NH * SEQ * 24;
        rope_kernel<<<(total + 255) / 256, 256>>>();
    }
    {   // attention (tensor cores)
        dim3 g((SEQ + 127) / 128, NH, NB);
        attn_mma_kernel<<<g, 256, attn_smem>>>();
    }
    {   // out = oa @ out_w + out_b + x
        dim3 g(DIMD / 128, (MROWS + 127) / 128);
        gemm_tf32<<<g, 256, gemm_smem>>>(oa, out_w, out_b, x, out, MROWS, DIMD, DIMD);
    }
}

// round 4
// speedup vs baseline: 5.2178x; 1.7742x over previous
#include <cuda_runtime.h>
#include <cuda_bf16.h>
#include <math.h>
#include <math_constants.h>
#include <stdint.h>

#define SEQ   1365
#define DIMD  1024
#define NH    16
#define HD    64
#define NB    8
#define MROWS (NB*SEQ)   // 10920

typedef __nv_bfloat16 bf16;

// ---------------- scratch ----------------------------------------------------
__device__ float g_wb [NB * 2 * DIMD];
__device__ bf16  g_xnh[ (size_t)MROWS * DIMD ];
__device__ bf16  g_wqkv[ (size_t)DIMD * 3 * DIMD ];
__device__ bf16  g_wout[ (size_t)DIMD * DIMD ];
__device__ float g_qkv[ (size_t)MROWS * 3 * DIMD ];
__device__ bf16  g_q  [ (size_t)NB * NH * SEQ * HD ];
__device__ bf16  g_k  [ (size_t)NB * NH * SEQ * HD ];
__device__ bf16  g_v  [ (size_t)NB * NH * SEQ * HD ];
__device__ bf16  g_oab[ (size_t)MROWS * DIMD ];

// ---------------- helpers ----------------------------------------------------
__device__ __forceinline__ int block_end(int s) {
    if (s < 1)   return 1;
    if (s < 5)   return 5;
    if (s < 21)  return 21;
    if (s < 85)  return 85;
    if (s < 341) return 341;
    return 1365;
}

__device__ __forceinline__ uint32_t pack_bf16(float lo, float hi) {
    __nv_bfloat162 h = __floats2bfloat162_rn(lo, hi);
    return *(uint32_t*)&h;
}

__device__ __forceinline__ void mma_bf16(float* c, const uint32_t* a, const uint32_t* b) {
    asm volatile(
        "mma.sync.aligned.m16n8k16.row.col.f32.bf16.bf16.f32 "
        "{%0,%1,%2,%3}, {%4,%5,%6,%7}, {%8,%9}, {%0,%1,%2,%3};"
        : "+f"(c[0]), "+f"(c[1]), "+f"(c[2]), "+f"(c[3])
        : "r"(a[0]), "r"(a[1]), "r"(a[2]), "r"(a[3]), "r"(b[0]), "r"(b[1]));
}

__device__ __forceinline__ void ldsm_x4(uint32_t* r, const void* p) {
    uint32_t a = (uint32_t)__cvta_generic_to_shared(p);
    asm volatile("ldmatrix.sync.aligned.m8n8.x4.shared.b16 {%0,%1,%2,%3}, [%4];"
        : "=r"(r[0]), "=r"(r[1]), "=r"(r[2]), "=r"(r[3]) : "r"(a));
}
__device__ __forceinline__ void ldsm_x4_t(uint32_t* r, const void* p) {
    uint32_t a = (uint32_t)__cvta_generic_to_shared(p);
    asm volatile("ldmatrix.sync.aligned.m8n8.x4.trans.shared.b16 {%0,%1,%2,%3}, [%4];"
        : "=r"(r[0]), "=r"(r[1]), "=r"(r[2]), "=r"(r[3]) : "r"(a));
}

__device__ __forceinline__ void cp16(void* s, const void* g) {
    uint32_t sa = (uint32_t)__cvta_generic_to_shared(s);
    asm volatile("cp.async.cg.shared.global [%0], [%1], 16;\n" :: "r"(sa), "l"(g));
}
__device__ __forceinline__ void cp_commit() { asm volatile("cp.async.commit_group;\n"); }
template <int N>
__device__ __forceinline__ void cp_wait() { asm volatile("cp.async.wait_group %0;\n" :: "n"(N)); }

// ---------------- adaLN ------------------------------------------------------
__global__ void adaln_kernel(const float* __restrict__ cond,
                             const float* __restrict__ w,
                             const float* __restrict__ bias) {
    __shared__ float c[256];
    int b = blockIdx.x;
    int t = threadIdx.x;
    c[t] = cond[b * 256 + t];
    __syncthreads();
    for (int j = t; j < 2048; j += 256) {
        float acc = bias[j];
        #pragma unroll 8
        for (int k = 0; k < 256; k++) acc += c[k] * w[k * 2048 + j];
        g_wb[b * 2048 + j] = acc;
    }
}

// ---------------- weight fp32 -> bf16 ----------------------------------------
__global__ void convw_kernel(const float* __restrict__ src, bf16* __restrict__ dst, int n4) {
    int i = blockIdx.x * blockDim.x + threadIdx.x;
    if (i >= n4) return;
    float4 v = ((const float4*)src)[i];
    uint2 o;
    o.x = pack_bf16(v.x, v.y);
    o.y = pack_bf16(v.z, v.w);
    ((uint2*)dst)[i] = o;
}

// ---------------- LayerNorm + modulate -> bf16 -------------------------------
__global__ void ln_kernel(const float* __restrict__ x) {
    int row = blockIdx.x;
    int b   = row / SEQ;
    int t   = threadIdx.x;
    const float4* xr = (const float4*)(x + (size_t)row * DIMD);
    float4 v = xr[t];
    float s  = v.x + v.y + v.z + v.w;
    float ss = v.x*v.x + v.y*v.y + v.z*v.z + v.w*v.w;
    #pragma unroll
    for (int o = 16; o > 0; o >>= 1) {
        s  += __shfl_down_sync(0xffffffffu, s,  o);
        ss += __shfl_down_sync(0xffffffffu, ss, o);
    }
    __shared__ float sh_s[8], sh_ss[8];
    int w = t >> 5, ln = t & 31;
    if (ln == 0) { sh_s[w] = s; sh_ss[w] = ss; }
    __syncthreads();
    if (w == 0) {
        s  = (ln < 8) ? sh_s[ln]  : 0.f;
        ss = (ln < 8) ? sh_ss[ln] : 0.f;
        #pragma unroll
        for (int o = 4; o > 0; o >>= 1) {
            s  += __shfl_down_sync(0xffffffffu, s,  o);
            ss += __shfl_down_sync(0xffffffffu, ss, o);
        }
        if (ln == 0) { sh_s[0] = s; sh_ss[0] = ss; }
    }
    __syncthreads();
    float mu   = sh_s[0]  * (1.0f / 1024.0f);
    float var  = sh_ss[0] * (1.0f / 1024.0f) - mu * mu;
    float rstd = rsqrtf(var + 1e-5f);
    const float4* wr = (const float4*)(g_wb + b * 2048);
    float4 wv = wr[t];
    float4 bv = wr[256 + t];
    float rx = (v.x - mu) * rstd * (wv.x + 1.0f) + bv.x;
    float ry = (v.y - mu) * rstd * (wv.y + 1.0f) + bv.y;
    float rz = (v.z - mu) * rstd * (wv.z + 1.0f) + bv.z;
    float rw = (v.w - mu) * rstd * (wv.w + 1.0f) + bv.w;
    uint2 o;
    o.x = pack_bf16(rx, ry);
    o.y = pack_bf16(rz, rw);
    ((uint2*)(g_xnh + (size_t)row * DIMD))[t] = o;
}

// ---------------- bf16 tensor-core GEMM: C(fp32) = A@B + bias (+skip) --------
// 128x128 tile, BK=32, 8 warps (2x4), warp tile 64x32, m16n8k16.
#define GASTR 40    // A smem stride (bf16)
#define GBSTR 136   // B smem stride (bf16)
#define GAS(buf,m,k) sA[(buf)*128*GASTR + (m)*GASTR + (k)]
#define GBS(buf,k,n) sB[(buf)*32*GBSTR + (k)*GBSTR + (n)]

__global__ __launch_bounds__(256)
void gemm_bf16(const bf16* __restrict__ A, const bf16* __restrict__ B,
               const float* __restrict__ bias, const float* __restrict__ skip,
               float* __restrict__ C, int M, int N, int K) {
    extern __shared__ bf16 smem[];
    bf16* sA = smem;                       // 2*128*40
    bf16* sB = smem + 2 * 128 * GASTR;     // 2*32*136

    const int t    = threadIdx.x;
    const int lane = t & 31;
    const int w    = t >> 5;
    const int wm   = (w >> 2) * 64;
    const int wn   = (w & 3) * 32;
    const int m0   = blockIdx.y * 128;
    const int n0   = blockIdx.x * 128;

    float acc[16][4];
    #pragma unroll
    for (int i = 0; i < 16; i++)
        #pragma unroll
        for (int j = 0; j < 4; j++) acc[i][j] = 0.f;

    const int NT = K / 32;

    auto load_tile = [&](int kt, int buf) {
        int k0 = kt * 32;
        #pragma unroll
        for (int i = 0; i < 4; i++) {
            int idx = t + 256 * i;
            if (i < 2) {
                // A: 128 rows x 4 chunks of 8 bf16
                int row = idx >> 2, seg = idx & 3;
                int gm  = min(m0 + row, M - 1);
                cp16(&GAS(buf, row, seg * 8), &A[(size_t)gm * K + k0 + seg * 8]);
            } else {
                // B: 32 rows x 16 chunks
                int j2   = idx - 512;
                int krow = j2 >> 4, nseg = j2 & 15;
                cp16(&GBS(buf, krow, nseg * 8), &B[(size_t)(k0 + krow) * N + n0 + nseg * 8]);
            }
        }
    };

    load_tile(0, 0);
    cp_commit();

    const int la15 = lane & 15;
    const int lhi  = lane >> 4;       // 0/1 -> col half
    const int l7   = lane & 7;
    const int lb   = (lane >> 3) & 1;

    for (int kt = 0; kt < NT; kt++) {
        int buf = kt & 1;
        if (kt + 1 < NT) {
            load_tile(kt + 1, buf ^ 1);
            cp_commit();
            cp_wait<1>();
        } else {
            cp_wait<0>();
        }
        __syncthreads();

        #pragma unroll
        for (int ks = 0; ks < 2; ks++) {
            uint32_t a[4][4];
            #pragma unroll
            for (int mt = 0; mt < 4; mt++)
                ldsm_x4(a[mt], &GAS(buf, wm + mt * 16 + la15, ks * 16 + lhi * 8));
            uint32_t bb[2][4];
            #pragma unroll
            for (int p = 0; p < 2; p++)
                ldsm_x4_t(bb[p], &GBS(buf, ks * 16 + lb * 8 + l7, wn + p * 16 + lhi * 8));
            #pragma unroll
            for (int mt = 0; mt < 4; mt++)
                #pragma unroll
                for (int nt = 0; nt < 4; nt++)
                    mma_bf16(acc[mt * 4 + nt], a[mt], &bb[nt >> 1][(nt & 1) * 2]);
        }
        __syncthreads();
    }

    #pragma unroll
    for (int mt = 0; mt < 4; mt++) {
        #pragma unroll
        for (int nt = 0; nt < 4; nt++) {
            float* cc = acc[mt * 4 + nt];
            int r  = m0 + wm + mt * 16 + (lane >> 2);
            int cb = n0 + wn + nt * 8 + 2 * (lane & 3);
            float b0 = bias[cb], b1 = bias[cb + 1];
            if (r < M) {
                float v0 = cc[0] + b0, v1 = cc[1] + b1;
                if (skip) {
                    v0 += skip[(size_t)r * N + cb];
                    v1 += skip[(size_t)r * N + cb + 1];
                }
                C[(size_t)r * N + cb]     = v0;
                C[(size_t)r * N + cb + 1] = v1;
            }
            if (r + 8 < M) {
                float v2 = cc[2] + b0, v3 = cc[3] + b1;
                if (skip) {
                    v2 += skip[(size_t)(r + 8) * N + cb];
                    v3 += skip[(size_t)(r + 8) * N + cb + 1];
                }
                C[(size_t)(r + 8) * N + cb]     = v2;
                C[(size_t)(r + 8) * N + cb + 1] = v3;
            }
        }
    }
}

// ---------------- fused RoPE + layout + bf16 convert -------------------------
// 1 block per token row. q scaled by 1/8. Outputs [b][h][s][64] bf16.
__global__ __launch_bounds__(256)
void rope_convert_kernel() {
    __shared__ float buf[3072];
    int row = blockIdx.x;
    int s   = row % SEQ;
    int b   = row / SEQ;
    const float4* src = (const float4*)(g_qkv + (size_t)row * 3072);
    float4* dstb = (float4*)buf;
    for (int i = threadIdx.x; i < 768; i += 256) dstb[i] = src[i];

    float ph = 0.f, pw = 0.f, pr = 0.f;
    if (s > 0) {
        int b5, n, start;
        if      (s < 5)   { b5 = 0; n = 2;  start = 1;   }
        else if (s < 21)  { b5 = 1; n = 4;  start = 5;   }
        else if (s < 85)  { b5 = 2; n = 8;  start = 21;  }
        else if (s < 341) { b5 = 3; n = 16; start = 85;  }
        else              { b5 = 4; n = 32; start = 341; }
        int li = s - start;
        int r  = li / n, c = li % n;
        ph = -1.0f + (float)(2 * r + 1) / (float)n;
        pw = -1.0f + (float)(2 * c + 1) / (float)n;
        pr = (float)(b5 + 1) / 5.0f;
    }
    __syncthreads();

    for (int u = threadIdx.x; u < 768; u += 256) {
        int dg = u & 15;
        int h  = (u >> 4) & 15;
        int which = u >> 8;          // 0=q 1=k 2=v
        int d0 = dg * 4;
        float out[4];
        #pragma unroll
        for (int j = 0; j < 4; j++) {
            int dd = d0 + j;
            float val;
            if (which == 2 || dd >= 48) {
                val = buf[which * 1024 + h * 64 + dd];
            } else {
                int jj = (dd < 24) ? dd : dd - 24;
                float x1 = buf[which * 1024 + h * 64 + jj];
                float x2 = buf[which * 1024 + h * 64 + jj + 24];
                int comp = jj >> 3, f = jj & 7;
                float p = (comp == 0) ? ph : ((comp == 1) ? pw : pr);
                float freq = (float)CUDART_PI_F * exp2f((float)(f * 16 + h) * (3.3219280948873623f / 128.0f));
                float th = p * freq;
                float sn, cs;
                __sincosf(th, &sn, &cs);
                val = (dd < 24) ? (x1 * cs - x2 * sn) : (x2 * cs + x1 * sn);
            }
            if (which == 0) val *= 0.125f;
            out[j] = val;
        }
        bf16* dst = (which == 0 ? g_q : (which == 1 ? g_k : g_v))
                    + ((size_t)(b * NH + h) * SEQ + s) * 64 + d0;
        uint2 o;
        o.x = pack_bf16(out[0], out[1]);
        o.y = pack_bf16(out[2], out[3]);
        *(uint2*)dst = o;
    }
}

// ---------------- bf16 tensor-core block-causal flash attention --------------
#define KSTR 72   // smem row stride (bf16)

__global__ __launch_bounds__(256)
void attn_bf16_kernel() {
    extern __shared__ bf16 sm[];
    bf16* sK = sm;                       // 2 * 64 * 72
    bf16* sV = sm + 2 * 64 * KSTR;

    const int t    = threadIdx.x;
    const int lane = t & 31;
    const int w    = t >> 5;
    const int qi   = lane & 3;
    const int gp   = lane >> 2;
    const int qt = blockIdx.x, h = blockIdx.y, b = blockIdx.z;
    const int q0 = qt * 128;
    const int rA = q0 + w * 16 + gp;
    const int rB = rA + 8;
    const int klimA = (rA < SEQ) ? block_end(rA) : 0;
    const int klimB = (rB < SEQ) ? block_end(rB) : 0;
    const int kmax  = block_end(min(q0 + 127, SEQ - 1));

    const size_t headQ = ((size_t)(b * NH + h)) * SEQ;

    // Q fragments: qf[ks] = {A(rA,2qi), A(rB,2qi), A(rA,2qi+8), A(rB,2qi+8)} pairs
    uint32_t qf[4][4];
    {
        const bf16* QA = g_q + (headQ + min(rA, SEQ - 1)) * 64;
        const bf16* QB = g_q + (headQ + min(rB, SEQ - 1)) * 64;
        #pragma unroll
        for (int ks = 0; ks < 4; ks++) {
            qf[ks][0] = *(const uint32_t*)(QA + ks * 16 + 2 * qi);
            qf[ks][1] = *(const uint32_t*)(QB + ks * 16 + 2 * qi);
            qf[ks][2] = *(const uint32_t*)(QA + ks * 16 + 2 * qi + 8);
            qf[ks][3] = *(const uint32_t*)(QB + ks * 16 + 2 * qi + 8);
        }
    }

    float o[8][4];
    #pragma unroll
    for (int i = 0; i < 8; i++)
        #pragma unroll
        for (int j = 0; j < 4; j++) o[i][j] = 0.f;
    float mA = -1e30f, mB = -1e30f, lA = 0.f, lB = 0.f;

    auto loadkv = [&](int kt_, int buf) {
        #pragma unroll
        for (int i = 0; i < 4; i++) {
            int idx = t + 256 * i;           // 1024 chunks
            int tensor = idx >> 9;           // 0=K 1=V
            int r   = (idx >> 3) & 63;
            int seg = idx & 7;
            int gk  = min(kt_ + r, SEQ - 1);
            const bf16* src = (tensor ? g_v : g_k) + (headQ + gk) * 64 + seg * 8;
            bf16* dst = (tensor ? sV : sK) + buf * 64 * KSTR + r * KSTR + seg * 8;
            cp16(dst, src);
        }
    };

    loadkv(0, 0);
    cp_commit();
    const int NIT = (kmax + 63) >> 6;

    for (int it = 0; it < NIT; it++) {
        const int kt_ = it * 64;
        const int buf = it & 1;
        if (it + 1 < NIT) {
            loadkv(kt_ + 64, buf ^ 1);
            cp_commit();
            cp_wait<1>();
        } else {
            cp_wait<0>();
        }
        __syncthreads();

        // S = Q @ K^T : sc[nt] covers keys nt*8..+7
        float sc[8][4];
        #pragma unroll
        for (int i = 0; i < 8; i++)
            #pragma unroll
            for (int j = 0; j < 4; j++) sc[i][j] = 0.f;
        const bf16* Kb = sK + buf * 64 * KSTR;
        #pragma unroll
        for (int ks = 0; ks < 4; ks++) {
            #pragma unroll
            for (int nt = 0; nt < 8; nt++) {
                const bf16* kp = Kb + (nt * 8 + gp) * KSTR + ks * 16 + 2 * qi;
                uint32_t bf[2];
                bf[0] = *(const uint32_t*)kp;
                bf[1] = *(const uint32_t*)(kp + 8);
                mma_bf16(sc[nt], qf[ks], bf);
            }
        }

        // mask + online softmax
        float nmA = mA, nmB = mB;
        #pragma unroll
        for (int nt = 0; nt < 8; nt++) {
            int c0 = kt_ + nt * 8 + 2 * qi;
            if (c0     >= klimA) sc[nt][0] = -1e30f;
            if (c0 + 1 >= klimA) sc[nt][1] = -1e30f;
            if (c0     >= klimB) sc[nt][2] = -1e30f;
            if (c0 + 1 >= klimB) sc[nt][3] = -1e30f;
            nmA = fmaxf(nmA, fmaxf(sc[nt][0], sc[nt][1]));
            nmB = fmaxf(nmB, fmaxf(sc[nt][2], sc[nt][3]));
        }
        nmA = fmaxf(nmA, __shfl_xor_sync(0xffffffffu, nmA, 1));
        nmA = fmaxf(nmA, __shfl_xor_sync(0xffffffffu, nmA, 2));
        nmB = fmaxf(nmB, __shfl_xor_sync(0xffffffffu, nmB, 1));
        nmB = fmaxf(nmB, __shfl_xor_sync(0xffffffffu, nmB, 2));
        float corrA = __expf(mA - nmA);
        float corrB = __expf(mB - nmB);
        mA = nmA; mB = nmB;
        lA *= corrA; lB *= corrB;
        #pragma unroll
        for (int nt = 0; nt < 8; nt++) {
            o[nt][0] *= corrA; o[nt][1] *= corrA;
            o[nt][2] *= corrB; o[nt][3] *= corrB;
        }
        #pragma unroll
        for (int nt = 0; nt < 8; nt++) {
            sc[nt][0] = __expf(sc[nt][0] - mA);
            sc[nt][1] = __expf(sc[nt][1] - mA);
            sc[nt][2] = __expf(sc[nt][2] - mB);
            sc[nt][3] = __expf(sc[nt][3] - mB);
            lA += sc[nt][0] + sc[nt][1];
            lB += sc[nt][2] + sc[nt][3];
        }

        // O += P @ V. P accum layout == bf16 A-operand layout (no shuffles).
        const bf16* Vb = sV + buf * 64 * KSTR;
        const int l7 = lane & 7;
        const int lb = (lane >> 3) & 1;
        const int lhi = lane >> 4;
        #pragma unroll
        for (int kb = 0; kb < 4; kb++) {
            uint32_t pa[4];
            pa[0] = pack_bf16(sc[2 * kb][0],     sc[2 * kb][1]);
            pa[1] = pack_bf16(sc[2 * kb][2],     sc[2 * kb][3]);
            pa[2] = pack_bf16(sc[2 * kb + 1][0], sc[2 * kb + 1][1]);
            pa[3] = pack_bf16(sc[2 * kb + 1][2], sc[2 * kb + 1][3]);
            #pragma unroll
            for (int p = 0; p < 4; p += 1) {
                if (p & 1) continue;  // process npairs 0,2 -> covers nt 0..3 each? (see below)
            }
            #pragma unroll
            for (int np = 0; np < 4; np++) {
                uint32_t vb[4];
                ldsm_x4_t(vb, Vb + (kb * 16 + lb * 8 + l7) * KSTR + np * 16 + lhi * 8);
                mma_bf16(o[2 * np],     pa, &vb[0]);
                mma_bf16(o[2 * np + 1], pa, &vb[2]);
            }
        }
        __syncthreads();
    }

    lA += __shfl_xor_sync(0xffffffffu, lA, 1);
    lA += __shfl_xor_sync(0xffffffffu, lA, 2);
    lB += __shfl_xor_sync(0xffffffffu, lB, 1);
    lB += __shfl_xor_sync(0xffffffffu, lB, 2);
    float invA = 1.0f / lA, invB = 1.0f / lB;

    if (rA < SEQ) {
        bf16* dst = g_oab + ((size_t)(b * SEQ + rA)) * 1024 + h * 64;
        #pragma unroll
        for (int nt = 0; nt < 8; nt++)
            *(uint32_t*)(dst + nt * 8 + 2 * qi) = pack_bf16(o[nt][0] * invA, o[nt][1] * invA);
    }
    if (rB < SEQ) {
        bf16* dst = g_oab + ((size_t)(b * SEQ + rB)) * 1024 + h * 64;
        #pragma unroll
        for (int nt = 0; nt < 8; nt++)
            *(uint32_t*)(dst + nt * 8 + 2 * qi) = pack_bf16(o[nt][2] * invB, o[nt][3] * invB);
    }
}

// ---------------- launch -----------------------------------------------------
extern "C" void kernel_launch(void* const* d_in, const int* in_sizes, int n_in,
                              void* d_out, int out_size) {
    const float* x       = (const float*)d_in[0];
    const float* cond    = (const float*)d_in[1];
    const float* adaln_w = (const float*)d_in[2];
    const float* adaln_b = (const float*)d_in[3];
    const float* qkv_w   = (const float*)d_in[4];
    const float* qkv_b   = (const float*)d_in[5];
    const float* out_w   = (const float*)d_in[6];
    const float* out_b   = (const float*)d_in[7];
    float* out = (float*)d_out;

    void *p_xnh, *p_wqkv, *p_wout, *p_qkv, *p_oab;
    cudaGetSymbolAddress(&p_xnh,  g_xnh);
    cudaGetSymbolAddress(&p_wqkv, g_wqkv);
    cudaGetSymbolAddress(&p_wout, g_wout);
    cudaGetSymbolAddress(&p_qkv,  g_qkv);
    cudaGetSymbolAddress(&p_oab,  g_oab);

    const int gemm_smem = (2 * 128 * GASTR + 2 * 32 * GBSTR) * 2;   // 37888 B
    cudaFuncSetAttribute(gemm_bf16, cudaFuncAttributeMaxDynamicSharedMemorySize, gemm_smem);
    const int attn_smem = 4 * 64 * KSTR * 2;                         // 36864 B
    cudaFuncSetAttribute(attn_bf16_kernel, cudaFuncAttributeMaxDynamicSharedMemorySize, attn_smem);

    adaln_kernel<<<NB, 256>>>(cond, adaln_w, adaln_b);
    ln_kernel<<<MROWS, 256>>>(x);
    convw_kernel<<<(1024 * 3072 / 4 + 255) / 256, 256>>>(qkv_w, (bf16*)p_wqkv, 1024 * 3072 / 4);
    convw_kernel<<<(1024 * 1024 / 4 + 255) / 256, 256>>>(out_w, (bf16*)p_wout, 1024 * 1024 / 4);

    {   // qkv = xn @ qkv_w + qkv_b  (fp32 out)
        dim3 g(3 * DIMD / 128, (MROWS + 127) / 128);
        gemm_bf16<<<g, 256, gemm_smem>>>((const bf16*)p_xnh, (const bf16*)p_wqkv,
                                         qkv_b, nullptr, (float*)p_qkv, MROWS, 3 * DIMD, DIMD);
    }
    rope_convert_kernel<<<MROWS, 256>>>();
    {   // attention
        dim3 g((SEQ + 127) / 128, NH, NB);
        attn_bf16_kernel<<<g, 256, attn_smem>>>();
    }
    {   // out = oa @ out_w + out_b + x
        dim3 g(DIMD / 128, (MROWS + 127) / 128);
        gemm_bf16<<<g, 256, gemm_smem>>>((const bf16*)p_oab, (const bf16*)p_wout,
                                         out_b, x, out, MROWS, DIMD, DIMD);
    }
}

// round 6
// speedup vs baseline: 5.5120x; 1.0564x over previous
#include <cuda_runtime.h>
#include <cuda_bf16.h>
#include <math.h>
#include <math_constants.h>
#include <stdint.h>

#define SEQ   1365
#define DIMD  1024
#define NH    16
#define HD    64
#define NB    8
#define MROWS (NB*SEQ)   // 10920

typedef __nv_bfloat16 bf16;

// ---------------- scratch ----------------------------------------------------
__device__ float g_wb  [NB * 2 * DIMD];
__device__ bf16  g_xnh [ (size_t)MROWS * DIMD ];
__device__ bf16  g_wqkv[ (size_t)DIMD * 3 * DIMD ];
__device__ bf16  g_wout[ (size_t)DIMD * DIMD ];
__device__ bf16  g_qkvh[ (size_t)MROWS * 3 * DIMD ];
__device__ bf16  g_q   [ (size_t)NB * NH * SEQ * HD ];
__device__ bf16  g_k   [ (size_t)NB * NH * SEQ * HD ];
__device__ bf16  g_v   [ (size_t)NB * NH * SEQ * HD ];
__device__ bf16  g_oab [ (size_t)MROWS * DIMD ];

// ---------------- helpers ----------------------------------------------------
__device__ __forceinline__ int block_end(int s) {
    if (s < 1)   return 1;
    if (s < 5)   return 5;
    if (s < 21)  return 21;
    if (s < 85)  return 85;
    if (s < 341) return 341;
    return 1365;
}

__device__ __forceinline__ uint32_t pack_bf16(float lo, float hi) {
    __nv_bfloat162 h = __floats2bfloat162_rn(lo, hi);
    return *(uint32_t*)&h;
}

__device__ __forceinline__ void mma_bf16(float* c, const uint32_t* a, const uint32_t* b) {
    asm volatile(
        "mma.sync.aligned.m16n8k16.row.col.f32.bf16.bf16.f32 "
        "{%0,%1,%2,%3}, {%4,%5,%6,%7}, {%8,%9}, {%0,%1,%2,%3};"
        : "+f"(c[0]), "+f"(c[1]), "+f"(c[2]), "+f"(c[3])
        : "r"(a[0]), "r"(a[1]), "r"(a[2]), "r"(a[3]), "r"(b[0]), "r"(b[1]));
}

__device__ __forceinline__ void ldsm_x4(uint32_t* r, const void* p) {
    uint32_t a = (uint32_t)__cvta_generic_to_shared(p);
    asm volatile("ldmatrix.sync.aligned.m8n8.x4.shared.b16 {%0,%1,%2,%3}, [%4];"
        : "=r"(r[0]), "=r"(r[1]), "=r"(r[2]), "=r"(r[3]) : "r"(a));
}
__device__ __forceinline__ void ldsm_x4_t(uint32_t* r, const void* p) {
    uint32_t a = (uint32_t)__cvta_generic_to_shared(p);
    asm volatile("ldmatrix.sync.aligned.m8n8.x4.trans.shared.b16 {%0,%1,%2,%3}, [%4];"
        : "=r"(r[0]), "=r"(r[1]), "=r"(r[2]), "=r"(r[3]) : "r"(a));
}

__device__ __forceinline__ void cp16(void* s, const void* g) {
    uint32_t sa = (uint32_t)__cvta_generic_to_shared(s);
    asm volatile("cp.async.cg.shared.global [%0], [%1], 16;\n" :: "r"(sa), "l"(g));
}
__device__ __forceinline__ void cp_commit() { asm volatile("cp.async.commit_group;\n"); }
template <int N>
__device__ __forceinline__ void cp_wait() { asm volatile("cp.async.wait_group %0;\n" :: "n"(N)); }

// ---------------- adaLN ------------------------------------------------------
__global__ void adaln_kernel(const float* __restrict__ cond,
                             const float* __restrict__ w,
                             const float* __restrict__ bias) {
    __shared__ float c[256];
    int b = blockIdx.x;
    int t = threadIdx.x;
    c[t] = cond[b * 256 + t];
    __syncthreads();
    for (int j = t; j < 2048; j += 256) {
        float acc = bias[j];
        #pragma unroll 8
        for (int k = 0; k < 256; k++) acc += c[k] * w[k * 2048 + j];
        g_wb[b * 2048 + j] = acc;
    }
}

// ---------------- weight fp32 -> bf16 ----------------------------------------
__global__ void convw_kernel(const float* __restrict__ src, bf16* __restrict__ dst, int n4) {
    int i = blockIdx.x * blockDim.x + threadIdx.x;
    if (i >= n4) return;
    float4 v = ((const float4*)src)[i];
    uint2 o;
    o.x = pack_bf16(v.x, v.y);
    o.y = pack_bf16(v.z, v.w);
    ((uint2*)dst)[i] = o;
}

// ---------------- LayerNorm + modulate -> bf16 -------------------------------
__global__ void ln_kernel(const float* __restrict__ x) {
    int row = blockIdx.x;
    int b   = row / SEQ;
    int t   = threadIdx.x;
    const float4* xr = (const float4*)(x + (size_t)row * DIMD);
    float4 v = xr[t];
    float s  = v.x + v.y + v.z + v.w;
    float ss = v.x*v.x + v.y*v.y + v.z*v.z + v.w*v.w;
    #pragma unroll
    for (int o = 16; o > 0; o >>= 1) {
        s  += __shfl_down_sync(0xffffffffu, s,  o);
        ss += __shfl_down_sync(0xffffffffu, ss, o);
    }
    __shared__ float sh_s[8], sh_ss[8];
    int w = t >> 5, ln = t & 31;
    if (ln == 0) { sh_s[w] = s; sh_ss[w] = ss; }
    __syncthreads();
    if (w == 0) {
        s  = (ln < 8) ? sh_s[ln]  : 0.f;
        ss = (ln < 8) ? sh_ss[ln] : 0.f;
        #pragma unroll
        for (int o = 4; o > 0; o >>= 1) {
            s  += __shfl_down_sync(0xffffffffu, s,  o);
            ss += __shfl_down_sync(0xffffffffu, ss, o);
        }
        if (ln == 0) { sh_s[0] = s; sh_ss[0] = ss; }
    }
    __syncthreads();
    float mu   = sh_s[0]  * (1.0f / 1024.0f);
    float var  = sh_ss[0] * (1.0f / 1024.0f) - mu * mu;
    float rstd = rsqrtf(var + 1e-5f);
    const float4* wr = (const float4*)(g_wb + b * 2048);
    float4 wv = wr[t];
    float4 bv = wr[256 + t];
    float rx = (v.x - mu) * rstd * (wv.x + 1.0f) + bv.x;
    float ry = (v.y - mu) * rstd * (wv.y + 1.0f) + bv.y;
    float rz = (v.z - mu) * rstd * (wv.z + 1.0f) + bv.z;
    float rw = (v.w - mu) * rstd * (wv.w + 1.0f) + bv.w;
    uint2 o;
    o.x = pack_bf16(rx, ry);
    o.y = pack_bf16(rz, rw);
    ((uint2*)(g_xnh + (size_t)row * DIMD))[t] = o;
}

// ---------------- bf16 mma.sync GEMM, 3-stage cp.async pipeline --------------
// 128x128 tile, BK=32, 8 warps (2x4), warp tile 64x32, m16n8k16.
// Output: bf16 (Ch) or fp32 (+skip) (Cf).
#define GASTR 40
#define GBSTR 136
#define GST   3
#define GAS(buf,m,k) sA[(buf)*128*GASTR + (m)*GASTR + (k)]
#define GBS(buf,k,n) sB[(buf)*32*GBSTR + (k)*GBSTR + (n)]

__global__ __launch_bounds__(256)
void gemm_bf16(const bf16* __restrict__ A, const bf16* __restrict__ B,
               const float* __restrict__ bias, const float* __restrict__ skip,
               float* __restrict__ Cf, bf16* __restrict__ Ch,
               int M, int N, int K) {
    extern __shared__ bf16 smem[];
    bf16* sA = smem;                          // GST*128*40
    bf16* sB = smem + GST * 128 * GASTR;      // GST*32*136

    const int t    = threadIdx.x;
    const int lane = t & 31;
    const int w    = t >> 5;
    const int wm   = (w >> 2) * 64;
    const int wn   = (w & 3) * 32;
    const int m0   = blockIdx.y * 128;
    const int n0   = blockIdx.x * 128;

    float acc[16][4];
    #pragma unroll
    for (int i = 0; i < 16; i++)
        #pragma unroll
        for (int j = 0; j < 4; j++) acc[i][j] = 0.f;

    const int NT = K / 32;

    auto load_tile = [&](int kt) {
        int buf = kt % GST;
        int k0  = kt * 32;
        #pragma unroll
        for (int i = 0; i < 4; i++) {
            int idx = t + 256 * i;
            if (i < 2) {
                int row = idx >> 2, seg = idx & 3;
                int gm  = min(m0 + row, M - 1);
                cp16(&GAS(buf, row, seg * 8), &A[(size_t)gm * K + k0 + seg * 8]);
            } else {
                int j2   = idx - 512;
                int krow = j2 >> 4, nseg = j2 & 15;
                cp16(&GBS(buf, krow, nseg * 8), &B[(size_t)(k0 + krow) * N + n0 + nseg * 8]);
            }
        }
    };

    load_tile(0); cp_commit();
    load_tile(1); cp_commit();

    const int la15 = lane & 15;
    const int lhi  = lane >> 4;
    const int l7   = lane & 7;
    const int lb   = (lane >> 3) & 1;

    for (int kt = 0; kt < NT; kt++) {
        cp_wait<1>();
        __syncthreads();
        int buf = kt % GST;

        #pragma unroll
        for (int ks = 0; ks < 2; ks++) {
            uint32_t a[4][4];
            #pragma unroll
            for (int mt = 0; mt < 4; mt++)
                ldsm_x4(a[mt], &GAS(buf, wm + mt * 16 + la15, ks * 16 + lhi * 8));
            uint32_t bb[2][4];
            #pragma unroll
            for (int p = 0; p < 2; p++)
                ldsm_x4_t(bb[p], &GBS(buf, ks * 16 + lb * 8 + l7, wn + p * 16 + lhi * 8));
            #pragma unroll
            for (int mt = 0; mt < 4; mt++)
                #pragma unroll
                for (int nt = 0; nt < 4; nt++)
                    mma_bf16(acc[mt * 4 + nt], a[mt], &bb[nt >> 1][(nt & 1) * 2]);
        }

        if (kt + 2 < NT) load_tile(kt + 2);
        cp_commit();
    }

    #pragma unroll
    for (int mt = 0; mt < 4; mt++) {
        #pragma unroll
        for (int nt = 0; nt < 4; nt++) {
            float* cc = acc[mt * 4 + nt];
            int r  = m0 + wm + mt * 16 + (lane >> 2);
            int cb = n0 + wn + nt * 8 + 2 * (lane & 3);
            float b0 = bias[cb], b1 = bias[cb + 1];
            if (Ch) {
                if (r < M)
                    *(uint32_t*)(Ch + (size_t)r * N + cb) = pack_bf16(cc[0] + b0, cc[1] + b1);
                if (r + 8 < M)
                    *(uint32_t*)(Ch + (size_t)(r + 8) * N + cb) = pack_bf16(cc[2] + b0, cc[3] + b1);
            } else {
                if (r < M) {
                    float v0 = cc[0] + b0, v1 = cc[1] + b1;
                    if (skip) {
                        v0 += skip[(size_t)r * N + cb];
                        v1 += skip[(size_t)r * N + cb + 1];
                    }
                    Cf[(size_t)r * N + cb]     = v0;
                    Cf[(size_t)r * N + cb + 1] = v1;
                }
                if (r + 8 < M) {
                    float v2 = cc[2] + b0, v3 = cc[3] + b1;
                    if (skip) {
                        v2 += skip[(size_t)(r + 8) * N + cb];
                        v3 += skip[(size_t)(r + 8) * N + cb + 1];
                    }
                    Cf[(size_t)(r + 8) * N + cb]     = v2;
                    Cf[(size_t)(r + 8) * N + cb + 1] = v3;
                }
            }
        }
    }
}

// ---------------- fused RoPE + layout + bf16 convert -------------------------
__global__ __launch_bounds__(256)
void rope_convert_kernel() {
    __shared__ float buf[3072];
    int row = blockIdx.x;
    int s   = row % SEQ;
    int b   = row / SEQ;
    const uint32_t* src = (const uint32_t*)(g_qkvh + (size_t)row * 3072);
    for (int i = threadIdx.x; i < 1536; i += 256) {
        uint32_t u = src[i];
        float2 f = __bfloat1622float2(*(__nv_bfloat162*)&u);
        buf[2 * i]     = f.x;
        buf[2 * i + 1] = f.y;
    }

    float ph = 0.f, pw = 0.f, pr = 0.f;
    if (s > 0) {
        int b5, n, start;
        if      (s < 5)   { b5 = 0; n = 2;  start = 1;   }
        else if (s < 21)  { b5 = 1; n = 4;  start = 5;   }
        else if (s < 85)  { b5 = 2; n = 8;  start = 21;  }
        else if (s < 341) { b5 = 3; n = 16; start = 85;  }
        else              { b5 = 4; n = 32; start = 341; }
        int li = s - start;
        int r  = li / n, c = li % n;
        ph = -1.0f + (float)(2 * r + 1) / (float)n;
        pw = -1.0f + (float)(2 * c + 1) / (float)n;
        pr = (float)(b5 + 1) / 5.0f;
    }
    __syncthreads();

    for (int u = threadIdx.x; u < 768; u += 256) {
        int dg = u & 15;
        int h  = (u >> 4) & 15;
        int which = u >> 8;          // 0=q 1=k 2=v
        int d0 = dg * 4;
        float out[4];
        #pragma unroll
        for (int j = 0; j < 4; j++) {
            int dd = d0 + j;
            float val;
            if (which == 2 || dd >= 48) {
                val = buf[which * 1024 + h * 64 + dd];
            } else {
                int jj = (dd < 24) ? dd : dd - 24;
                float x1 = buf[which * 1024 + h * 64 + jj];
                float x2 = buf[which * 1024 + h * 64 + jj + 24];
                int comp = jj >> 3, f = jj & 7;
                float p = (comp == 0) ? ph : ((comp == 1) ? pw : pr);
                float freq = (float)CUDART_PI_F * exp2f((float)(f * 16 + h) * (3.3219280948873623f / 128.0f));
                float th = p * freq;
                float sn, cs;
                __sincosf(th, &sn, &cs);
                val = (dd < 24) ? (x1 * cs - x2 * sn) : (x2 * cs + x1 * sn);
            }
            if (which == 0) val *= 0.125f;
            out[j] = val;
        }
        bf16* dst = (which == 0 ? g_q : (which == 1 ? g_k : g_v))
                    + ((size_t)(b * NH + h) * SEQ + s) * 64 + d0;
        uint2 o;
        o.x = pack_bf16(out[0], out[1]);
        o.y = pack_bf16(out[2], out[3]);
        *(uint2*)dst = o;
    }
}

// ---------------- bf16 mma.sync block-causal flash attention -----------------
#define KSTR 72   // smem row stride (bf16)

__global__ __launch_bounds__(256)
void attn_bf16_kernel() {
    extern __shared__ bf16 sm[];
    bf16* sK = sm;
    bf16* sV = sm + 2 * 64 * KSTR;

    const int t    = threadIdx.x;
    const int lane = t & 31;
    const int w    = t >> 5;
    const int qi   = lane & 3;
    const int gp   = lane >> 2;
    const int qt = blockIdx.x, h = blockIdx.y, b = blockIdx.z;
    const int q0 = qt * 128;
    const int rA = q0 + w * 16 + gp;
    const int rB = rA + 8;
    const int klimA = (rA < SEQ) ? block_end(rA) : 0;
    const int klimB = (rB < SEQ) ? block_end(rB) : 0;
    const int kmax  = block_end(min(q0 + 127, SEQ - 1));

    const size_t headQ = ((size_t)(b * NH + h)) * SEQ;

    uint32_t qf[4][4];
    {
        const bf16* QA = g_q + (headQ + min(rA, SEQ - 1)) * 64;
        const bf16* QB = g_q + (headQ + min(rB, SEQ - 1)) * 64;
        #pragma unroll
        for (int ks = 0; ks < 4; ks++) {
            qf[ks][0] = *(const uint32_t*)(QA + ks * 16 + 2 * qi);
            qf[ks][1] = *(const uint32_t*)(QB + ks * 16 + 2 * qi);
            qf[ks][2] = *(const uint32_t*)(QA + ks * 16 + 2 * qi + 8);
            qf[ks][3] = *(const uint32_t*)(QB + ks * 16 + 2 * qi + 8);
        }
    }

    float o[8][4];
    #pragma unroll
    for (int i = 0; i < 8; i++)
        #pragma unroll
        for (int j = 0; j < 4; j++) o[i][j] = 0.f;
    float mA = -1e30f, mB = -1e30f, lA = 0.f, lB = 0.f;

    auto loadkv = [&](int kt_, int buf) {
        #pragma unroll
        for (int i = 0; i < 4; i++) {
            int idx = t + 256 * i;
            int tensor = idx >> 9;
            int r   = (idx >> 3) & 63;
            int seg = idx & 7;
            int gk  = min(kt_ + r, SEQ - 1);
            const bf16* src = (tensor ? g_v : g_k) + (headQ + gk) * 64 + seg * 8;
            bf16* dst = (tensor ? sV : sK) + buf * 64 * KSTR + r * KSTR + seg * 8;
            cp16(dst, src);
        }
    };

    loadkv(0, 0);
    cp_commit();
    const int NIT = (kmax + 63) >> 6;

    for (int it = 0; it < NIT; it++) {
        const int kt_ = it * 64;
        const int buf = it & 1;
        if (it + 1 < NIT) {
            loadkv(kt_ + 64, buf ^ 1);
            cp_commit();
            cp_wait<1>();
        } else {
            cp_wait<0>();
        }
        __syncthreads();

        float sc[8][4];
        #pragma unroll
        for (int i = 0; i < 8; i++)
            #pragma unroll
            for (int j = 0; j < 4; j++) sc[i][j] = 0.f;
        const bf16* Kb = sK + buf * 64 * KSTR;
        #pragma unroll
        for (int ks = 0; ks < 4; ks++) {
            #pragma unroll
            for (int nt = 0; nt < 8; nt++) {
                const bf16* kp = Kb + (nt * 8 + gp) * KSTR + ks * 16 + 2 * qi;
                uint32_t bf[2];
                bf[0] = *(const uint32_t*)kp;
                bf[1] = *(const uint32_t*)(kp + 8);
                mma_bf16(sc[nt], qf[ks], bf);
            }
        }

        float nmA = mA, nmB = mB;
        #pragma unroll
        for (int nt = 0; nt < 8; nt++) {
            int c0 = kt_ + nt * 8 + 2 * qi;
            if (c0     >= klimA) sc[nt][0] = -1e30f;
            if (c0 + 1 >= klimA) sc[nt][1] = -1e30f;
            if (c0     >= klimB) sc[nt][2] = -1e30f;
            if (c0 + 1 >= klimB) sc[nt][3] = -1e30f;
            nmA = fmaxf(nmA, fmaxf(sc[nt][0], sc[nt][1]));
            nmB = fmaxf(nmB, fmaxf(sc[nt][2], sc[nt][3]));
        }
        nmA = fmaxf(nmA, __shfl_xor_sync(0xffffffffu, nmA, 1));
        nmA = fmaxf(nmA, __shfl_xor_sync(0xffffffffu, nmA, 2));
        nmB = fmaxf(nmB, __shfl_xor_sync(0xffffffffu, nmB, 1));
        nmB = fmaxf(nmB, __shfl_xor_sync(0xffffffffu, nmB, 2));
        float corrA = __expf(mA - nmA);
        float corrB = __expf(mB - nmB);
        mA = nmA; mB = nmB;
        lA *= corrA; lB *= corrB;
        #pragma unroll
        for (int nt = 0; nt < 8; nt++) {
            o[nt][0] *= corrA; o[nt][1] *= corrA;
            o[nt][2] *= corrB; o[nt][3] *= corrB;
        }
        #pragma unroll
        for (int nt = 0; nt < 8; nt++) {
            sc[nt][0] = __expf(sc[nt][0] - mA);
            sc[nt][1] = __expf(sc[nt][1] - mA);
            sc[nt][2] = __expf(sc[nt][2] - mB);
            sc[nt][3] = __expf(sc[nt][3] - mB);
            lA += sc[nt][0] + sc[nt][1];
            lB += sc[nt][2] + sc[nt][3];
        }

        const bf16* Vb = sV + buf * 64 * KSTR;
        const int l7 = lane & 7;
        const int lb = (lane >> 3) & 1;
        const int lhi = lane >> 4;
        #pragma unroll
        for (int kb = 0; kb < 4; kb++) {
            uint32_t pa[4];
            pa[0] = pack_bf16(sc[2 * kb][0],     sc[2 * kb][1]);
            pa[1] = pack_bf16(sc[2 * kb][2],     sc[2 * kb][3]);
            pa[2] = pack_bf16(sc[2 * kb + 1][0], sc[2 * kb + 1][1]);
            pa[3] = pack_bf16(sc[2 * kb + 1][2], sc[2 * kb + 1][3]);
            #pragma unroll
            for (int np = 0; np < 4; np++) {
                uint32_t vb[4];
                ldsm_x4_t(vb, Vb + (kb * 16 + lb * 8 + l7) * KSTR + np * 16 + lhi * 8);
                mma_bf16(o[2 * np],     pa, &vb[0]);
                mma_bf16(o[2 * np + 1], pa, &vb[2]);
            }
        }
        __syncthreads();
    }

    lA += __shfl_xor_sync(0xffffffffu, lA, 1);
    lA += __shfl_xor_sync(0xffffffffu, lA, 2);
    lB += __shfl_xor_sync(0xffffffffu, lB, 1);
    lB += __shfl_xor_sync(0xffffffffu, lB, 2);
    float invA = 1.0f / lA, invB = 1.0f / lB;

    if (rA < SEQ) {
        bf16* dst = g_oab + ((size_t)(b * SEQ + rA)) * 1024 + h * 64;
        #pragma unroll
        for (int nt = 0; nt < 8; nt++)
            *(uint32_t*)(dst + nt * 8 + 2 * qi) = pack_bf16(o[nt][0] * invA, o[nt][1] * invA);
    }
    if (rB < SEQ) {
        bf16* dst = g_oab + ((size_t)(b * SEQ + rB)) * 1024 + h * 64;
        #pragma unroll
        for (int nt = 0; nt < 8; nt++)
            *(uint32_t*)(dst + nt * 8 + 2 * qi) = pack_bf16(o[nt][2] * invB, o[nt][3] * invB);
    }
}

// ---------------- launch -----------------------------------------------------
extern "C" void kernel_launch(void* const* d_in, const int* in_sizes, int n_in,
                              void* d_out, int out_size) {
    const float* x       = (const float*)d_in[0];
    const float* cond    = (const float*)d_in[1];
    const float* adaln_w = (const float*)d_in[2];
    const float* adaln_b = (const float*)d_in[3];
    const float* qkv_w   = (const float*)d_in[4];
    const float* qkv_b   = (const float*)d_in[5];
    const float* out_w   = (const float*)d_in[6];
    const float* out_b   = (const float*)d_in[7];
    float* out = (float*)d_out;

    void *p_xnh, *p_wqkv, *p_wout, *p_qkvh, *p_oab;
    cudaGetSymbolAddress(&p_xnh,  g_xnh);
    cudaGetSymbolAddress(&p_wqkv, g_wqkv);
    cudaGetSymbolAddress(&p_wout, g_wout);
    cudaGetSymbolAddress(&p_qkvh, g_qkvh);
    cudaGetSymbolAddress(&p_oab,  g_oab);

    const int gemm_smem = (GST * 128 * GASTR + GST * 32 * GBSTR) * 2;   // 56832 B
    cudaFuncSetAttribute(gemm_bf16, cudaFuncAttributeMaxDynamicSharedMemorySize, gemm_smem);
    const int attn_smem = 4 * 64 * KSTR * 2;                            // 36864 B
    cudaFuncSetAttribute(attn_bf16_kernel, cudaFuncAttributeMaxDynamicSharedMemorySize, attn_smem);

    adaln_kernel<<<NB, 256>>>(cond, adaln_w, adaln_b);
    ln_kernel<<<MROWS, 256>>>(x);
    convw_kernel<<<(1024 * 3072 / 4 + 255) / 256, 256>>>(qkv_w, (bf16*)p_wqkv, 1024 * 3072 / 4);
    convw_kernel<<<(1024 * 1024 / 4 + 255) / 256, 256>>>(out_w, (bf16*)p_wout, 1024 * 1024 / 4);

    {   // qkv = xn @ qkv_w + qkv_b  -> bf16 directly
        dim3 g(3 * DIMD / 128, (MROWS + 127) / 128);
        gemm_bf16<<<g, 256, gemm_smem>>>((const bf16*)p_xnh, (const bf16*)p_wqkv,
                                         qkv_b, nullptr, nullptr, (bf16*)p_qkvh,
                                         MROWS, 3 * DIMD, DIMD);
    }
    rope_convert_kernel<<<MROWS, 256>>>();
    {   // attention
        dim3 g((SEQ + 127) / 128, NH, NB);
        attn_bf16_kernel<<<g, 256, attn_smem>>>();
    }
    {   // out = oa @ out_w + out_b + x  -> fp32
        dim3 g(DIMD / 128, (MROWS + 127) / 128);
        gemm_bf16<<<g, 256, gemm_smem>>>((const bf16*)p_oab, (const bf16*)p_wout,
                                         out_b, x, out, nullptr,
                                         MROWS, DIMD, DIMD);
    }
}